// round 9
// baseline (speedup 1.0000x reference)
#include <cuda_runtime.h>
#include <math.h>
#include <stdint.h>

#define BQ    8
#define TSZ   288
#define NSZ   2000
#define NP    2048
#define FLSZ  145
#define FPAD  160
#define ESZ   128
#define IDSZ  16
#define DSZ   144
#define HSZ   128
#define KTOP  20
#define NHB   (NSZ*HSZ)

// ---------------- scratch (__device__ globals: allocation-free, zero-init) ----
__device__ float g_cos[FPAD*TSZ];
__device__ float g_sin[FPAD*TSZ];
__device__ float g_xf  [BQ*FLSZ*NSZ];
__device__ float g_invn[BQ*FLSZ];
__device__ float g_invf[BQ*NSZ];
__device__ float g_xe  [BQ*NSZ*ESZ];
__device__ float g_x1  [(size_t)BQ*NP*HSZ];
__device__ float g_mu  [BQ];
__device__ float g_rstd[BQ];
__device__ float g_wcs [HSZ];
__device__ float g_adp [(size_t)BQ*NP*HSZ];
__device__ float g_adj [(size_t)BQ*NSZ*NSZ];

// ---------------- helpers ----------------
__device__ __forceinline__ void msplit(float x, float& hi, float& lo) {
    uint32_t hb = __float_as_uint(x) & 0xFFFFE000u;
    float hf = __uint_as_float(hb);
    hi = hf; lo = x - hf;
}
__device__ __forceinline__ void mma_tf32(float* c, const uint32_t* a, const uint32_t* b) {
    asm volatile(
        "mma.sync.aligned.m16n8k8.row.col.f32.tf32.tf32.f32 "
        "{%0,%1,%2,%3}, {%4,%5,%6,%7}, {%8,%9}, {%0,%1,%2,%3};"
        : "+f"(c[0]), "+f"(c[1]), "+f"(c[2]), "+f"(c[3])
        : "r"(a[0]), "r"(a[1]), "r"(a[2]), "r"(a[3]), "r"(b[0]), "r"(b[1]));
}
__device__ __forceinline__ void cp16(void* smem_dst, const void* gmem_src) {
    unsigned sa = (unsigned)__cvta_generic_to_shared(smem_dst);
    asm volatile("cp.async.ca.shared.global [%0], [%1], 16;\n" :: "r"(sa), "l"(gmem_src));
}
__device__ __forceinline__ void cp_commit() { asm volatile("cp.async.commit_group;\n"); }
template<int N> __device__ __forceinline__ void cp_wait() {
    asm volatile("cp.async.wait_group %0;\n" :: "n"(N));
}

__global__ void k_dummy() {}

// ---------------- 1. DFT basis (exact integer phase reduction) ---------------
__global__ void k_basis() {
    int i = blockIdx.x * blockDim.x + threadIdx.x;
    if (i < FLSZ * TSZ) {
        int f = i / TSZ, t = i % TSZ;
        int m = (f * t) % TSZ;
        float ang = (float)((double)m * 6.283185307179586 / (double)TSZ);
        int o = f * TSZ + t;
        g_cos[o] = cosf(ang);
        g_sin[o] = sinf(ang);
    }
}

// ---------------- 2. |rfft| via tf32x3 mma, raw smem, frag-time split --------
#define XP 33
#define BP 36
__global__ void __launch_bounds__(256) k_dft(const float* __restrict__ x) {
    __shared__ float Xs[128 * XP];
    __shared__ float Cs[32 * BP];
    __shared__ float Ss[32 * BP];
    int b  = blockIdx.z;
    int n0 = blockIdx.x * 128;
    int f0 = blockIdx.y * 32;
    int tid = threadIdx.x;
    int lane = tid & 31, w = tid >> 5;
    int wm = (w >> 2) * 16;
    int wn = (w & 3) * 32;

    float accR[4][4], accI[4][4];
    #pragma unroll
    for (int ni = 0; ni < 4; ++ni)
        #pragma unroll
        for (int q = 0; q < 4; ++q) { accR[ni][q] = 0.f; accI[ni][q] = 0.f; }

    for (int t0 = 0; t0 < TSZ; t0 += 32) {
        __syncthreads();
        #pragma unroll
        for (int q = 0; q < 2; ++q) {
            int idx = tid + q * 256;
            int a = idx >> 8, rem = idx & 255;
            int r = rem >> 3, c = rem & 7;
            float* dst = a ? Ss : Cs;
            const float* src = a ? g_sin : g_cos;
            cp16(dst + r * BP + c * 4, src + (f0 + r) * TSZ + t0 + c * 4);
        }
        cp_commit();
        #pragma unroll
        for (int tj = 0; tj < 4; ++tj) {
            int t = w * 4 + tj;
            #pragma unroll
            for (int ng = 0; ng < 4; ++ng) {
                int nl = ng * 32 + lane;
                int gn = n0 + nl;
                Xs[nl * XP + t] = (gn < NSZ) ? x[((size_t)b * TSZ + t0 + t) * NSZ + gn] : 0.f;
            }
        }
        cp_wait<0>();
        __syncthreads();

        #pragma unroll
        for (int ks = 0; ks < 4; ++ks) {
            int kc = ks * 8 + (lane & 3);
            int oa = (wm + (lane >> 2)) * BP + kc;
            uint32_t ChF[4], ClF[4], ShF[4], SlF[4];
            {
                float h, l;
                msplit(Cs[oa],              h, l); ChF[0] = __float_as_uint(h); ClF[0] = __float_as_uint(l);
                msplit(Cs[oa + 8 * BP],     h, l); ChF[1] = __float_as_uint(h); ClF[1] = __float_as_uint(l);
                msplit(Cs[oa + 4],          h, l); ChF[2] = __float_as_uint(h); ClF[2] = __float_as_uint(l);
                msplit(Cs[oa + 8 * BP + 4], h, l); ChF[3] = __float_as_uint(h); ClF[3] = __float_as_uint(l);
                msplit(Ss[oa],              h, l); ShF[0] = __float_as_uint(h); SlF[0] = __float_as_uint(l);
                msplit(Ss[oa + 8 * BP],     h, l); ShF[1] = __float_as_uint(h); SlF[1] = __float_as_uint(l);
                msplit(Ss[oa + 4],          h, l); ShF[2] = __float_as_uint(h); SlF[2] = __float_as_uint(l);
                msplit(Ss[oa + 8 * BP + 4], h, l); ShF[3] = __float_as_uint(h); SlF[3] = __float_as_uint(l);
            }
            #pragma unroll
            for (int ni = 0; ni < 4; ++ni) {
                int ob = (wn + ni * 8 + (lane >> 2)) * XP + kc;
                float h0, l0, h1, l1;
                msplit(Xs[ob],     h0, l0);
                msplit(Xs[ob + 4], h1, l1);
                uint32_t XhF[2] = {__float_as_uint(h0), __float_as_uint(h1)};
                uint32_t XlF[2] = {__float_as_uint(l0), __float_as_uint(l1)};
                mma_tf32(accR[ni], ChF, XhF);
                mma_tf32(accR[ni], ChF, XlF);
                mma_tf32(accR[ni], ClF, XhF);
                mma_tf32(accI[ni], ShF, XhF);
                mma_tf32(accI[ni], ShF, XlF);
                mma_tf32(accI[ni], SlF, XhF);
            }
        }
    }

    int fr = f0 + wm + (lane >> 2);
    #pragma unroll
    for (int ni = 0; ni < 4; ++ni) {
        int cN = n0 + wn + ni * 8 + ((lane & 3) << 1);
        if (fr < FLSZ) {
            float* p = &g_xf[(b * FLSZ + fr) * NSZ];
            if (cN     < NSZ) p[cN]     = sqrtf(accR[ni][0]*accR[ni][0] + accI[ni][0]*accI[ni][0]);
            if (cN + 1 < NSZ) p[cN + 1] = sqrtf(accR[ni][1]*accR[ni][1] + accI[ni][1]*accI[ni][1]);
        }
        if (fr + 8 < FLSZ) {
            float* p = &g_xf[(b * FLSZ + fr + 8) * NSZ];
            if (cN     < NSZ) p[cN]     = sqrtf(accR[ni][2]*accR[ni][2] + accI[ni][2]*accI[ni][2]);
            if (cN + 1 < NSZ) p[cN + 1] = sqrtf(accR[ni][3]*accR[ni][3] + accI[ni][3]*accI[ni][3]);
        }
    }
}

// ---------------- 3. norm over nodes (axis=1) ----------------
__global__ void k_invn() {
    int f = blockIdx.x, b = blockIdx.y;
    const float* p = &g_xf[(b * FLSZ + f) * NSZ];
    float s = 0.f;
    for (int i = threadIdx.x; i < NSZ; i += 256) { float v = p[i]; s += v * v; }
    __shared__ float red[256];
    red[threadIdx.x] = s; __syncthreads();
    for (int st = 128; st > 0; st >>= 1) {
        if (threadIdx.x < st) red[threadIdx.x] += red[threadIdx.x + st];
        __syncthreads();
    }
    if (threadIdx.x == 0)
        g_invn[b * FLSZ + f] = 1.f / fmaxf(sqrtf(red[0]), 1e-12f);
}

// ---------------- 4. norm over freq (axis=2) ----------------
__global__ void k_invf() {
    int b = blockIdx.y;
    int nl = threadIdx.x & 63;
    int n  = blockIdx.x * 64 + nl;
    int fp = threadIdx.x >> 6;
    float s = 0.f;
    if (n < NSZ)
        for (int f = fp; f < FLSZ; f += 4) {
            float v = g_xf[(b * FLSZ + f) * NSZ + n] * g_invn[b * FLSZ + f];
            s += v * v;
        }
    __shared__ float red[256];
    red[threadIdx.x] = s; __syncthreads();
    if (threadIdx.x < 64 && n < NSZ) {
        s = red[nl] + red[nl + 64] + red[nl + 128] + red[nl + 192];
        g_invf[b * NSZ + n] = 1.f / fmaxf(sqrtf(s), 1e-12f);
    }
}

// ---------------- 5. xe = normalized(xf) @ Ex via tf32x3 mma -----------------
#define XE_SMEM (4*128*BP*4)
__global__ void __launch_bounds__(512) k_xe(const float* __restrict__ Ex) {
    extern __shared__ float xsm[];
    float* Ah = xsm;
    float* Al = Ah + 128 * BP;
    float* Bh = Al + 128 * BP;
    float* Bl = Bh + 128 * BP;
    int b = blockIdx.z, n0 = blockIdx.x * 128;
    int tid = threadIdx.x;
    int lane = tid & 31, w = tid >> 5;
    int wm = (w >> 2) * 32;
    int wn = (w & 3) * 32;

    float acc[2][4][4];
    #pragma unroll
    for (int mi = 0; mi < 2; ++mi)
        #pragma unroll
        for (int ni = 0; ni < 4; ++ni)
            #pragma unroll
            for (int q = 0; q < 4; ++q) acc[mi][ni][q] = 0.f;

    for (int f0 = 0; f0 < FPAD; f0 += 32) {
        __syncthreads();
        #pragma unroll
        for (int q = 0; q < 8; ++q) {
            int idx = tid + q * 512;
            int fc = idx >> 7, nl = idx & 127;
            int f = f0 + fc, gn = n0 + nl;
            float val = 0.f;
            if (f < FLSZ && gn < NSZ)
                val = g_xf[(b * FLSZ + f) * NSZ + gn] * g_invn[b * FLSZ + f];
            float h, l; msplit(val, h, l);
            Ah[nl * BP + fc] = h; Al[nl * BP + fc] = l;
        }
        #pragma unroll
        for (int q = 0; q < 8; ++q) {
            int idx = tid + q * 512;
            int fc = idx >> 7, e = idx & 127;
            int f = f0 + fc;
            float val = (f < FLSZ) ? Ex[f * ESZ + e] : 0.f;
            float h, l; msplit(val, h, l);
            Bh[e * BP + fc] = h; Bl[e * BP + fc] = l;
        }
        __syncthreads();
        #pragma unroll
        for (int ks = 0; ks < 4; ++ks) {
            int kc = ks * 8 + (lane & 3);
            uint32_t AhF[2][4], AlF[2][4], BhF[4][2], BlF[4][2];
            #pragma unroll
            for (int mi = 0; mi < 2; ++mi) {
                int o = (wm + mi * 16 + (lane >> 2)) * BP + kc;
                AhF[mi][0] = __float_as_uint(Ah[o]);     AhF[mi][1] = __float_as_uint(Ah[o + 8 * BP]);
                AhF[mi][2] = __float_as_uint(Ah[o + 4]); AhF[mi][3] = __float_as_uint(Ah[o + 8 * BP + 4]);
                AlF[mi][0] = __float_as_uint(Al[o]);     AlF[mi][1] = __float_as_uint(Al[o + 8 * BP]);
                AlF[mi][2] = __float_as_uint(Al[o + 4]); AlF[mi][3] = __float_as_uint(Al[o + 8 * BP + 4]);
            }
            #pragma unroll
            for (int ni = 0; ni < 4; ++ni) {
                int o = (wn + ni * 8 + (lane >> 2)) * BP + kc;
                BhF[ni][0] = __float_as_uint(Bh[o]); BhF[ni][1] = __float_as_uint(Bh[o + 4]);
                BlF[ni][0] = __float_as_uint(Bl[o]); BlF[ni][1] = __float_as_uint(Bl[o + 4]);
            }
            #pragma unroll
            for (int mi = 0; mi < 2; ++mi)
                #pragma unroll
                for (int ni = 0; ni < 4; ++ni) {
                    mma_tf32(acc[mi][ni], AhF[mi], BhF[ni]);
                    mma_tf32(acc[mi][ni], AhF[mi], BlF[ni]);
                    mma_tf32(acc[mi][ni], AlF[mi], BhF[ni]);
                }
        }
    }

    #pragma unroll
    for (int mi = 0; mi < 2; ++mi) {
        int r0 = n0 + wm + mi * 16 + (lane >> 2);
        #pragma unroll
        for (int ni = 0; ni < 4; ++ni) {
            int c = wn + ni * 8 + ((lane & 3) << 1);
            float* C = acc[mi][ni];
            if (r0 < NSZ) {
                float sc = g_invf[b * NSZ + r0];
                float* p = &g_xe[((size_t)b * NSZ + r0) * ESZ];
                p[c] = C[0] * sc; p[c + 1] = C[1] * sc;
            }
            if (r0 + 8 < NSZ) {
                float sc = g_invf[b * NSZ + r0 + 8];
                float* p = &g_xe[((size_t)b * NSZ + r0 + 8) * ESZ];
                p[c] = C[2] * sc; p[c + 1] = C[3] * sc;
            }
        }
    }
}

// ---------------- 6. x1 = relu(per-node [8,144]@[144,128]) -------------------
__global__ void k_x1(const float* __restrict__ nodes, const float* __restrict__ Wd) {
    __shared__ float xk[BQ][DSZ];
    int n = blockIdx.x;
    int h = threadIdx.x;
    for (int idx = h; idx < BQ * ESZ; idx += 128) {
        int bb = idx >> 7, e = idx & 127;
        xk[bb][e] = g_xe[(bb * NSZ + n) * ESZ + e];
    }
    for (int idx = h; idx < BQ * IDSZ; idx += 128) {
        int bb = idx >> 4, i2 = idx & 15;
        xk[bb][ESZ + i2] = nodes[n * IDSZ + i2];
    }
    __syncthreads();
    float acc[BQ] = {};
    const float* wp = &Wd[(size_t)n * DSZ * HSZ + h];
    #pragma unroll 4
    for (int d = 0; d < DSZ; ++d) {
        float w = wp[d * HSZ];
        #pragma unroll
        for (int bb = 0; bb < BQ; ++bb) acc[bb] += xk[bb][d] * w;
    }
    #pragma unroll
    for (int bb = 0; bb < BQ; ++bb)
        g_x1[((size_t)bb * NP + n) * HSZ + h] = fmaxf(acc[bb], 0.f);
}

// ---------------- 7. LN stats over (N,H) per batch ----------------
__global__ void k_ln() {
    int b = blockIdx.x;
    const float* p = &g_x1[(size_t)b * NP * HSZ];
    double s = 0.0, q = 0.0;
    for (int i = threadIdx.x; i < NP * HSZ; i += 512) {
        float v = p[i]; s += v; q += (double)v * v;
    }
    __shared__ double rs[512], rq[512];
    rs[threadIdx.x] = s; rq[threadIdx.x] = q; __syncthreads();
    for (int st = 256; st > 0; st >>= 1) {
        if (threadIdx.x < st) { rs[threadIdx.x] += rs[threadIdx.x + st]; rq[threadIdx.x] += rq[threadIdx.x + st]; }
        __syncthreads();
    }
    if (threadIdx.x == 0) {
        double mu  = rs[0] / (double)NHB;
        double var = rq[0] / (double)NHB - mu * mu;
        g_mu[b]   = (float)mu;
        g_rstd[b] = (float)(1.0 / sqrt(var + 1e-8));
    }
}

// ---------------- 8. column sums of Wxabs ----------------
__global__ void k_wcs(const float* __restrict__ W) {
    int k = threadIdx.x;
    float s = 0.f;
    for (int h = 0; h < HSZ; ++h) s += W[h * HSZ + k];
    g_wcs[k] = s;
}

// ---------------- 9. adp = LN(x1) @ Wxabs (LN fused) ----------------
__global__ void k_adp(const float* __restrict__ W) {
    __shared__ float As[16][132];
    __shared__ float Bs[16][128];
    int b = blockIdx.z, n0 = blockIdx.x * 128;
    int tid = threadIdx.x, tx = tid & 15, ty = tid >> 4;
    float acc[8][8] = {};
    for (int k0 = 0; k0 < HSZ; k0 += 16) {
        for (int idx = tid; idx < 2048; idx += 256) {
            int r = idx >> 4, c = idx & 15;
            int n = n0 + r;
            As[c][r] = g_x1[((size_t)b * NP + n) * HSZ + k0 + c];
        }
        for (int idx = tid; idx < 2048; idx += 256) {
            int r = idx >> 7, c = idx & 127;
            Bs[r][c] = W[(k0 + r) * HSZ + c];
        }
        __syncthreads();
        #pragma unroll
        for (int kk = 0; kk < 16; ++kk) {
            float a[8], bv[8];
            *(float4*)&a[0]  = *(const float4*)&As[kk][ty * 8];
            *(float4*)&a[4]  = *(const float4*)&As[kk][ty * 8 + 4];
            *(float4*)&bv[0] = *(const float4*)&Bs[kk][tx * 8];
            *(float4*)&bv[4] = *(const float4*)&Bs[kk][tx * 8 + 4];
            #pragma unroll
            for (int i = 0; i < 8; ++i)
                #pragma unroll
                for (int j = 0; j < 8; ++j) acc[i][j] += a[i] * bv[j];
        }
        __syncthreads();
    }
    float mu = g_mu[b], rstd = g_rstd[b];
    #pragma unroll
    for (int i = 0; i < 8; ++i) {
        int n = n0 + ty * 8 + i;
        if (n >= NSZ) continue;
        #pragma unroll
        for (int j = 0; j < 8; ++j) {
            int k = tx * 8 + j;
            g_adp[((size_t)b * NP + n) * HSZ + k] = rstd * (acc[i][j] - mu * g_wcs[k]);
        }
    }
}

// ---------------- 10. adj: tf32x3 mma, raw cp.async dbuf, frag-time split ----
#define SPITCH 36
#define RAWSZ  (128*SPITCH)
#define ADJ_SMEM (4*RAWSZ*4)   // rawA[2] + rawB[2] = 73728 bytes

__global__ void __launch_bounds__(512) k_adj() {
    extern __shared__ float sm[];
    float* rawA = sm;
    float* rawB = sm + 2 * RAWSZ;
    int b  = blockIdx.z;
    int n0 = blockIdx.y * 128;
    int m0 = blockIdx.x * 128;
    int tid = threadIdx.x;
    int lane = tid & 31, w = tid >> 5;
    int wm = (w >> 2) * 32;
    int wn = (w & 3) * 32;

    const float* Ag = &g_adp[((size_t)b * NP + n0) * HSZ];
    const float* Bg = &g_x1 [((size_t)b * NP + m0) * HSZ];

    float acc[2][4][4];
    #pragma unroll
    for (int mi = 0; mi < 2; ++mi)
        #pragma unroll
        for (int ni = 0; ni < 4; ++ni)
            #pragma unroll
            for (int q = 0; q < 4; ++q) acc[mi][ni][q] = 0.f;

    #pragma unroll
    for (int q = 0; q < 2; ++q) {
        int idx = tid + q * 512;
        int r = idx >> 3, c = (idx & 7) * 4;
        cp16(&rawA[r * SPITCH + c], &Ag[(size_t)r * HSZ + c]);
        cp16(&rawB[r * SPITCH + c], &Bg[(size_t)r * HSZ + c]);
    }
    cp_commit();

    for (int kt = 0; kt < 4; ++kt) {
        int buf = kt & 1;
        if (kt + 1 < 4) {
            int k0 = (kt + 1) * 32;
            float* dA = rawA + (buf ^ 1) * RAWSZ;
            float* dB = rawB + (buf ^ 1) * RAWSZ;
            #pragma unroll
            for (int q = 0; q < 2; ++q) {
                int idx = tid + q * 512;
                int r = idx >> 3, c = (idx & 7) * 4;
                cp16(&dA[r * SPITCH + c], &Ag[(size_t)r * HSZ + k0 + c]);
                cp16(&dB[r * SPITCH + c], &Bg[(size_t)r * HSZ + k0 + c]);
            }
            cp_commit();
            cp_wait<1>();
        } else {
            cp_wait<0>();
        }
        __syncthreads();

        const float* cA = rawA + buf * RAWSZ;
        const float* cB = rawB + buf * RAWSZ;
        #pragma unroll
        for (int ks = 0; ks < 4; ++ks) {
            int kc = ks * 8 + (lane & 3);
            uint32_t AhF[2][4], AlF[2][4], BhF[4][2], BlF[4][2];
            #pragma unroll
            for (int mi = 0; mi < 2; ++mi) {
                int o = (wm + mi * 16 + (lane >> 2)) * SPITCH + kc;
                float h, l;
                msplit(cA[o],                  h, l); AhF[mi][0] = __float_as_uint(h); AlF[mi][0] = __float_as_uint(l);
                msplit(cA[o + 8 * SPITCH],     h, l); AhF[mi][1] = __float_as_uint(h); AlF[mi][1] = __float_as_uint(l);
                msplit(cA[o + 4],              h, l); AhF[mi][2] = __float_as_uint(h); AlF[mi][2] = __float_as_uint(l);
                msplit(cA[o + 8 * SPITCH + 4], h, l); AhF[mi][3] = __float_as_uint(h); AlF[mi][3] = __float_as_uint(l);
            }
            #pragma unroll
            for (int ni = 0; ni < 4; ++ni) {
                int o = (wn + ni * 8 + (lane >> 2)) * SPITCH + kc;
                float h, l;
                msplit(cB[o],     h, l); BhF[ni][0] = __float_as_uint(h); BlF[ni][0] = __float_as_uint(l);
                msplit(cB[o + 4], h, l); BhF[ni][1] = __float_as_uint(h); BlF[ni][1] = __float_as_uint(l);
            }
            #pragma unroll
            for (int mi = 0; mi < 2; ++mi)
                #pragma unroll
                for (int ni = 0; ni < 4; ++ni) {
                    mma_tf32(acc[mi][ni], AhF[mi], BhF[ni]);
                    mma_tf32(acc[mi][ni], AhF[mi], BlF[ni]);
                    mma_tf32(acc[mi][ni], AlF[mi], BhF[ni]);
                }
        }
        __syncthreads();
    }

    float* abase = &g_adj[(size_t)b * NSZ * NSZ];
    #pragma unroll
    for (int mi = 0; mi < 2; ++mi) {
        int r = n0 + wm + mi * 16 + (lane >> 2);
        #pragma unroll
        for (int ni = 0; ni < 4; ++ni) {
            int c = m0 + wn + ni * 8 + ((lane & 3) << 1);
            float* C = acc[mi][ni];
            if (r < NSZ) {
                float* row = abase + (size_t)r * NSZ;
                if (c     < NSZ) row[c]     = fmaxf(C[0], 0.f);
                if (c + 1 < NSZ) row[c + 1] = fmaxf(C[1], 0.f);
            }
            if (r + 8 < NSZ) {
                float* row = abase + (size_t)(r + 8) * NSZ;
                if (c     < NSZ) row[c]     = fmaxf(C[2], 0.f);
                if (c + 1 < NSZ) row[c + 1] = fmaxf(C[3], 0.f);
            }
        }
    }
}

// ---------------- 11. per-row exact radix-select top-20 + softmax ------------
// Histogram atomics are warp-aggregated via __match_any_sync: adj values share
// a narrow exponent range, so un-aggregated atomicAdd serializes on one bin.
#define MAXEQ 64
__global__ void __launch_bounds__(256) k_topk(float* __restrict__ out) {
    int n = blockIdx.x, b = blockIdx.y, tid = threadIdx.x;
    int lane = tid & 31;
    const float* row = &g_adj[((size_t)b * NSZ + n) * NSZ];

    unsigned v[8];
    #pragma unroll
    for (int j = 0; j < 8; ++j) {
        int m = tid + j * 256;
        v[j] = (m < NSZ) ? __float_as_uint(row[m]) : 0u;
    }

    __shared__ unsigned hist[256];
    __shared__ unsigned s_bin, s_kneed, s_maxb;
    __shared__ unsigned warpmax[8];
    __shared__ float s_red[256];
    __shared__ float sD;
    __shared__ int eqn, eqselN;
    __shared__ int eqlist[MAXEQ];
    __shared__ int eqsel[KTOP];

    unsigned mx = v[0];
    #pragma unroll
    for (int j = 1; j < 8; ++j) mx = max(mx, v[j]);
    #pragma unroll
    for (int s = 16; s; s >>= 1) mx = max(mx, __shfl_xor_sync(0xffffffffu, mx, s));
    if (!lane) warpmax[tid >> 5] = mx;
    if (tid == 0) eqn = 0;
    __syncthreads();
    if (tid == 0) {
        unsigned m2 = warpmax[0];
        #pragma unroll
        for (int i = 1; i < 8; ++i) m2 = max(m2, warpmax[i]);
        s_maxb = m2;
    }

    unsigned prefix = 0, mask = 0, Kneed = KTOP;
    #pragma unroll
    for (int pass = 0; pass < 4; ++pass) {
        int shift = 24 - pass * 8;
        __syncthreads();
        hist[tid] = 0;
        __syncthreads();
        #pragma unroll
        for (int j = 0; j < 8; ++j) {
            int m = tid + j * 256;
            bool act = (m < NSZ) && ((v[j] & mask) == prefix);
            int bin = act ? (int)((v[j] >> shift) & 255) : (256 + lane);
            unsigned peers = __match_any_sync(0xffffffffu, bin);
            if (act) {
                int leader = __ffs(peers) - 1;
                if (lane == leader) atomicAdd(&hist[bin], (unsigned)__popc(peers));
            }
        }
        __syncthreads();
        if (tid < 32) {
            unsigned s = 0;
            #pragma unroll
            for (int k = 0; k < 8; ++k) s += hist[tid * 8 + k];
            unsigned suf = s;
            #pragma unroll
            for (int d = 1; d < 32; d <<= 1) {
                unsigned o = __shfl_down_sync(0xffffffffu, suf, d);
                if (tid + d < 32) suf += o;
            }
            unsigned above = suf - s;
            if (above < Kneed && above + s >= Kneed) {
                unsigned cum = above;
                for (int k = 7; k >= 0; --k) {
                    unsigned h = hist[tid * 8 + k];
                    if (cum + h >= Kneed) { s_bin = tid * 8 + k; s_kneed = Kneed - cum; break; }
                    cum += h;
                }
            }
        }
        __syncthreads();
        prefix |= s_bin << shift;
        mask   |= 0xFFu << shift;
        Kneed   = s_kneed;
    }
    unsigned T = prefix;
    float Tf   = __uint_as_float(T);
    float vmax = __uint_as_float(s_maxb);

    #pragma unroll
    for (int j = 0; j < 8; ++j) {
        int m = tid + j * 256;
        if (m < NSZ && v[j] == T) {
            int p = atomicAdd(&eqn, 1);
            if (p < MAXEQ) eqlist[p] = m;
        }
    }
    __syncthreads();
    if (tid == 0) {
        int cnt = eqn < MAXEQ ? eqn : MAXEQ;
        int need = (int)Kneed; if (need > KTOP) need = KTOP;
        int sel = 0;
        for (int a = 0; a < need && a < cnt; ++a) {
            int bi = a;
            for (int c = a + 1; c < cnt; ++c) if (eqlist[c] < eqlist[bi]) bi = c;
            int t2 = eqlist[a]; eqlist[a] = eqlist[bi]; eqlist[bi] = t2;
            eqsel[a] = eqlist[a]; ++sel;
        }
        eqselN = sel;
    }
    __syncthreads();

    float s = 0.f;
    #pragma unroll
    for (int j = 0; j < 8; ++j) {
        int m = tid + j * 256;
        if (m < NSZ && v[j] > T) s += expf(__uint_as_float(v[j]) - vmax);
    }
    s_red[tid] = s; __syncthreads();
    for (int st = 128; st; st >>= 1) {
        if (tid < st) s_red[tid] += s_red[tid + st];
        __syncthreads();
    }
    if (tid == 0)
        sD = s_red[0] + (float)eqselN * expf(Tf - vmax)
           + (float)(NSZ - KTOP) * expf(-vmax);
    __syncthreads();

    float D = sD;
    float base = expf(-vmax) / D;
    float* orow = &out[((size_t)b * NSZ + n) * NSZ];
    float4 b4 = make_float4(base, base, base, base);
    for (int i = tid; i < NSZ / 4; i += 256) ((float4*)orow)[i] = b4;
    __syncthreads();
    int nEq = eqselN;
    #pragma unroll
    for (int j = 0; j < 8; ++j) {
        int m = tid + j * 256;
        if (m < NSZ) {
            if (v[j] > T) {
                orow[m] = expf(__uint_as_float(v[j]) - vmax) / D;
            } else if (v[j] == T) {
                for (int a = 0; a < nEq; ++a)
                    if (eqsel[a] == m) { orow[m] = expf(Tf - vmax) / D; break; }
            }
        }
    }
}

// ---------------- launch ----------------
extern "C" void kernel_launch(void* const* d_in, const int* in_sizes, int n_in,
                              void* d_out, int out_size) {
    const float* x     = (const float*)d_in[0];
    const float* Ex    = (const float*)d_in[1];
    const float* nodes = (const float*)d_in[2];
    const float* Wd    = (const float*)d_in[3];
    const float* W     = (const float*)d_in[4];
    float* out = (float*)d_out;

    cudaFuncSetAttribute(k_xe,  cudaFuncAttributeMaxDynamicSharedMemorySize, XE_SMEM);
    cudaFuncSetAttribute(k_adj, cudaFuncAttributeMaxDynamicSharedMemorySize, ADJ_SMEM);

    k_basis<<<(FLSZ * TSZ + 255) / 256, 256>>>();
    k_dummy<<<1, 32>>>();
    k_dummy<<<1, 32>>>();                       // k_dft stays at ncu capture index
    k_dft  <<<dim3(16, 5, BQ), 256>>>(x);
    k_invn <<<dim3(FLSZ, BQ), 256>>>();
    k_invf <<<dim3((NSZ + 63) / 64, BQ), 256>>>();
    k_xe   <<<dim3(16, 1, BQ), 512, XE_SMEM>>>(Ex);
    k_x1   <<<NSZ, 128>>>(nodes, Wd);
    k_ln   <<<BQ, 512>>>();
    k_wcs  <<<1, 128>>>(W);
    k_adp  <<<dim3(16, 1, BQ), 256>>>(W);
    k_adj  <<<dim3(16, 16, BQ), 512, ADJ_SMEM>>>();
    k_topk <<<dim3(NSZ, BQ), 256>>>(out);
}

// round 10
// speedup vs baseline: 1.8881x; 1.8881x over previous
#include <cuda_runtime.h>
#include <math.h>
#include <stdint.h>

#define BQ    8
#define TSZ   288
#define NSZ   2000
#define NP    2048
#define FLSZ  145
#define FPAD  160
#define ESZ   128
#define IDSZ  16
#define DSZ   144
#define HSZ   128
#define KTOP  20
#define NHB   (NSZ*HSZ)

// ---------------- scratch (__device__ globals: allocation-free, zero-init) ----
__device__ float g_cos[FPAD*TSZ];
__device__ float g_sin[FPAD*TSZ];
__device__ float g_xf  [BQ*FLSZ*NSZ];
__device__ float g_invn[BQ*FLSZ];
__device__ float g_invf[BQ*NSZ];
__device__ float g_xe  [BQ*NSZ*ESZ];
__device__ float g_x1  [(size_t)BQ*NP*HSZ];
__device__ float g_mu  [BQ];
__device__ float g_rstd[BQ];
__device__ float g_wcs [HSZ];
__device__ float g_adp [(size_t)BQ*NP*HSZ];
__device__ float g_adj [(size_t)BQ*NSZ*NSZ];

// ---------------- helpers ----------------
__device__ __forceinline__ void msplit(float x, float& hi, float& lo) {
    uint32_t hb = __float_as_uint(x) & 0xFFFFE000u;
    float hf = __uint_as_float(hb);
    hi = hf; lo = x - hf;
}
__device__ __forceinline__ void mma_tf32(float* c, const uint32_t* a, const uint32_t* b) {
    asm volatile(
        "mma.sync.aligned.m16n8k8.row.col.f32.tf32.tf32.f32 "
        "{%0,%1,%2,%3}, {%4,%5,%6,%7}, {%8,%9}, {%0,%1,%2,%3};"
        : "+f"(c[0]), "+f"(c[1]), "+f"(c[2]), "+f"(c[3])
        : "r"(a[0]), "r"(a[1]), "r"(a[2]), "r"(a[3]), "r"(b[0]), "r"(b[1]));
}
__device__ __forceinline__ void cp16(void* smem_dst, const void* gmem_src) {
    unsigned sa = (unsigned)__cvta_generic_to_shared(smem_dst);
    asm volatile("cp.async.ca.shared.global [%0], [%1], 16;\n" :: "r"(sa), "l"(gmem_src));
}
__device__ __forceinline__ void cp_commit() { asm volatile("cp.async.commit_group;\n"); }
template<int N> __device__ __forceinline__ void cp_wait() {
    asm volatile("cp.async.wait_group %0;\n" :: "n"(N));
}

__global__ void k_dummy() {}

// ---------------- 1. DFT basis (exact integer phase reduction) ---------------
__global__ void k_basis() {
    int i = blockIdx.x * blockDim.x + threadIdx.x;
    if (i < FLSZ * TSZ) {
        int f = i / TSZ, t = i % TSZ;
        int m = (f * t) % TSZ;
        float ang = (float)((double)m * 6.283185307179586 / (double)TSZ);
        int o = f * TSZ + t;
        g_cos[o] = cosf(ang);
        g_sin[o] = sinf(ang);
    }
}

// ---------------- 2. |rfft| via tf32x3 mma, raw smem, frag-time split --------
#define XP 33
#define BP 36
__global__ void __launch_bounds__(256) k_dft(const float* __restrict__ x) {
    __shared__ float Xs[128 * XP];
    __shared__ float Cs[32 * BP];
    __shared__ float Ss[32 * BP];
    int b  = blockIdx.z;
    int n0 = blockIdx.x * 128;
    int f0 = blockIdx.y * 32;
    int tid = threadIdx.x;
    int lane = tid & 31, w = tid >> 5;
    int wm = (w >> 2) * 16;
    int wn = (w & 3) * 32;

    float accR[4][4], accI[4][4];
    #pragma unroll
    for (int ni = 0; ni < 4; ++ni)
        #pragma unroll
        for (int q = 0; q < 4; ++q) { accR[ni][q] = 0.f; accI[ni][q] = 0.f; }

    for (int t0 = 0; t0 < TSZ; t0 += 32) {
        __syncthreads();
        #pragma unroll
        for (int q = 0; q < 2; ++q) {
            int idx = tid + q * 256;
            int a = idx >> 8, rem = idx & 255;
            int r = rem >> 3, c = rem & 7;
            float* dst = a ? Ss : Cs;
            const float* src = a ? g_sin : g_cos;
            cp16(dst + r * BP + c * 4, src + (f0 + r) * TSZ + t0 + c * 4);
        }
        cp_commit();
        #pragma unroll
        for (int tj = 0; tj < 4; ++tj) {
            int t = w * 4 + tj;
            #pragma unroll
            for (int ng = 0; ng < 4; ++ng) {
                int nl = ng * 32 + lane;
                int gn = n0 + nl;
                Xs[nl * XP + t] = (gn < NSZ) ? x[((size_t)b * TSZ + t0 + t) * NSZ + gn] : 0.f;
            }
        }
        cp_wait<0>();
        __syncthreads();

        #pragma unroll
        for (int ks = 0; ks < 4; ++ks) {
            int kc = ks * 8 + (lane & 3);
            int oa = (wm + (lane >> 2)) * BP + kc;
            uint32_t ChF[4], ClF[4], ShF[4], SlF[4];
            {
                float h, l;
                msplit(Cs[oa],              h, l); ChF[0] = __float_as_uint(h); ClF[0] = __float_as_uint(l);
                msplit(Cs[oa + 8 * BP],     h, l); ChF[1] = __float_as_uint(h); ClF[1] = __float_as_uint(l);
                msplit(Cs[oa + 4],          h, l); ChF[2] = __float_as_uint(h); ClF[2] = __float_as_uint(l);
                msplit(Cs[oa + 8 * BP + 4], h, l); ChF[3] = __float_as_uint(h); ClF[3] = __float_as_uint(l);
                msplit(Ss[oa],              h, l); ShF[0] = __float_as_uint(h); SlF[0] = __float_as_uint(l);
                msplit(Ss[oa + 8 * BP],     h, l); ShF[1] = __float_as_uint(h); SlF[1] = __float_as_uint(l);
                msplit(Ss[oa + 4],          h, l); ShF[2] = __float_as_uint(h); SlF[2] = __float_as_uint(l);
                msplit(Ss[oa + 8 * BP + 4], h, l); ShF[3] = __float_as_uint(h); SlF[3] = __float_as_uint(l);
            }
            #pragma unroll
            for (int ni = 0; ni < 4; ++ni) {
                int ob = (wn + ni * 8 + (lane >> 2)) * XP + kc;
                float h0, l0, h1, l1;
                msplit(Xs[ob],     h0, l0);
                msplit(Xs[ob + 4], h1, l1);
                uint32_t XhF[2] = {__float_as_uint(h0), __float_as_uint(h1)};
                uint32_t XlF[2] = {__float_as_uint(l0), __float_as_uint(l1)};
                mma_tf32(accR[ni], ChF, XhF);
                mma_tf32(accR[ni], ChF, XlF);
                mma_tf32(accR[ni], ClF, XhF);
                mma_tf32(accI[ni], ShF, XhF);
                mma_tf32(accI[ni], ShF, XlF);
                mma_tf32(accI[ni], SlF, XhF);
            }
        }
    }

    int fr = f0 + wm + (lane >> 2);
    #pragma unroll
    for (int ni = 0; ni < 4; ++ni) {
        int cN = n0 + wn + ni * 8 + ((lane & 3) << 1);
        if (fr < FLSZ) {
            float* p = &g_xf[(b * FLSZ + fr) * NSZ];
            if (cN     < NSZ) p[cN]     = sqrtf(accR[ni][0]*accR[ni][0] + accI[ni][0]*accI[ni][0]);
            if (cN + 1 < NSZ) p[cN + 1] = sqrtf(accR[ni][1]*accR[ni][1] + accI[ni][1]*accI[ni][1]);
        }
        if (fr + 8 < FLSZ) {
            float* p = &g_xf[(b * FLSZ + fr + 8) * NSZ];
            if (cN     < NSZ) p[cN]     = sqrtf(accR[ni][2]*accR[ni][2] + accI[ni][2]*accI[ni][2]);
            if (cN + 1 < NSZ) p[cN + 1] = sqrtf(accR[ni][3]*accR[ni][3] + accI[ni][3]*accI[ni][3]);
        }
    }
}

// ---------------- 3. norm over nodes (axis=1) ----------------
__global__ void k_invn() {
    int f = blockIdx.x, b = blockIdx.y;
    const float* p = &g_xf[(b * FLSZ + f) * NSZ];
    float s = 0.f;
    for (int i = threadIdx.x; i < NSZ; i += 256) { float v = p[i]; s += v * v; }
    __shared__ float red[256];
    red[threadIdx.x] = s; __syncthreads();
    for (int st = 128; st > 0; st >>= 1) {
        if (threadIdx.x < st) red[threadIdx.x] += red[threadIdx.x + st];
        __syncthreads();
    }
    if (threadIdx.x == 0)
        g_invn[b * FLSZ + f] = 1.f / fmaxf(sqrtf(red[0]), 1e-12f);
}

// ---------------- 4. norm over freq (axis=2) ----------------
__global__ void k_invf() {
    int b = blockIdx.y;
    int nl = threadIdx.x & 63;
    int n  = blockIdx.x * 64 + nl;
    int fp = threadIdx.x >> 6;
    float s = 0.f;
    if (n < NSZ)
        for (int f = fp; f < FLSZ; f += 4) {
            float v = g_xf[(b * FLSZ + f) * NSZ + n] * g_invn[b * FLSZ + f];
            s += v * v;
        }
    __shared__ float red[256];
    red[threadIdx.x] = s; __syncthreads();
    if (threadIdx.x < 64 && n < NSZ) {
        s = red[nl] + red[nl + 64] + red[nl + 128] + red[nl + 192];
        g_invf[b * NSZ + n] = 1.f / fmaxf(sqrtf(s), 1e-12f);
    }
}

// ---------------- 5. xe = normalized(xf) @ Ex via tf32x3 mma -----------------
#define XE_SMEM (4*128*BP*4)
__global__ void __launch_bounds__(512) k_xe(const float* __restrict__ Ex) {
    extern __shared__ float xsm[];
    float* Ah = xsm;
    float* Al = Ah + 128 * BP;
    float* Bh = Al + 128 * BP;
    float* Bl = Bh + 128 * BP;
    int b = blockIdx.z, n0 = blockIdx.x * 128;
    int tid = threadIdx.x;
    int lane = tid & 31, w = tid >> 5;
    int wm = (w >> 2) * 32;
    int wn = (w & 3) * 32;

    float acc[2][4][4];
    #pragma unroll
    for (int mi = 0; mi < 2; ++mi)
        #pragma unroll
        for (int ni = 0; ni < 4; ++ni)
            #pragma unroll
            for (int q = 0; q < 4; ++q) acc[mi][ni][q] = 0.f;

    for (int f0 = 0; f0 < FPAD; f0 += 32) {
        __syncthreads();
        #pragma unroll
        for (int q = 0; q < 8; ++q) {
            int idx = tid + q * 512;
            int fc = idx >> 7, nl = idx & 127;
            int f = f0 + fc, gn = n0 + nl;
            float val = 0.f;
            if (f < FLSZ && gn < NSZ)
                val = g_xf[(b * FLSZ + f) * NSZ + gn] * g_invn[b * FLSZ + f];
            float h, l; msplit(val, h, l);
            Ah[nl * BP + fc] = h; Al[nl * BP + fc] = l;
        }
        #pragma unroll
        for (int q = 0; q < 8; ++q) {
            int idx = tid + q * 512;
            int fc = idx >> 7, e = idx & 127;
            int f = f0 + fc;
            float val = (f < FLSZ) ? Ex[f * ESZ + e] : 0.f;
            float h, l; msplit(val, h, l);
            Bh[e * BP + fc] = h; Bl[e * BP + fc] = l;
        }
        __syncthreads();
        #pragma unroll
        for (int ks = 0; ks < 4; ++ks) {
            int kc = ks * 8 + (lane & 3);
            uint32_t AhF[2][4], AlF[2][4], BhF[4][2], BlF[4][2];
            #pragma unroll
            for (int mi = 0; mi < 2; ++mi) {
                int o = (wm + mi * 16 + (lane >> 2)) * BP + kc;
                AhF[mi][0] = __float_as_uint(Ah[o]);     AhF[mi][1] = __float_as_uint(Ah[o + 8 * BP]);
                AhF[mi][2] = __float_as_uint(Ah[o + 4]); AhF[mi][3] = __float_as_uint(Ah[o + 8 * BP + 4]);
                AlF[mi][0] = __float_as_uint(Al[o]);     AlF[mi][1] = __float_as_uint(Al[o + 8 * BP]);
                AlF[mi][2] = __float_as_uint(Al[o + 4]); AlF[mi][3] = __float_as_uint(Al[o + 8 * BP + 4]);
            }
            #pragma unroll
            for (int ni = 0; ni < 4; ++ni) {
                int o = (wn + ni * 8 + (lane >> 2)) * BP + kc;
                BhF[ni][0] = __float_as_uint(Bh[o]); BhF[ni][1] = __float_as_uint(Bh[o + 4]);
                BlF[ni][0] = __float_as_uint(Bl[o]); BlF[ni][1] = __float_as_uint(Bl[o + 4]);
            }
            #pragma unroll
            for (int mi = 0; mi < 2; ++mi)
                #pragma unroll
                for (int ni = 0; ni < 4; ++ni) {
                    mma_tf32(acc[mi][ni], AhF[mi], BhF[ni]);
                    mma_tf32(acc[mi][ni], AhF[mi], BlF[ni]);
                    mma_tf32(acc[mi][ni], AlF[mi], BhF[ni]);
                }
        }
    }

    #pragma unroll
    for (int mi = 0; mi < 2; ++mi) {
        int r0 = n0 + wm + mi * 16 + (lane >> 2);
        #pragma unroll
        for (int ni = 0; ni < 4; ++ni) {
            int c = wn + ni * 8 + ((lane & 3) << 1);
            float* C = acc[mi][ni];
            if (r0 < NSZ) {
                float sc = g_invf[b * NSZ + r0];
                float* p = &g_xe[((size_t)b * NSZ + r0) * ESZ];
                p[c] = C[0] * sc; p[c + 1] = C[1] * sc;
            }
            if (r0 + 8 < NSZ) {
                float sc = g_invf[b * NSZ + r0 + 8];
                float* p = &g_xe[((size_t)b * NSZ + r0 + 8) * ESZ];
                p[c] = C[2] * sc; p[c + 1] = C[3] * sc;
            }
        }
    }
}

// ---------------- 6. x1 = relu(per-node [8,144]@[144,128]) -------------------
__global__ void k_x1(const float* __restrict__ nodes, const float* __restrict__ Wd) {
    __shared__ float xk[BQ][DSZ];
    int n = blockIdx.x;
    int h = threadIdx.x;
    for (int idx = h; idx < BQ * ESZ; idx += 128) {
        int bb = idx >> 7, e = idx & 127;
        xk[bb][e] = g_xe[(bb * NSZ + n) * ESZ + e];
    }
    for (int idx = h; idx < BQ * IDSZ; idx += 128) {
        int bb = idx >> 4, i2 = idx & 15;
        xk[bb][ESZ + i2] = nodes[n * IDSZ + i2];
    }
    __syncthreads();
    float acc[BQ] = {};
    const float* wp = &Wd[(size_t)n * DSZ * HSZ + h];
    #pragma unroll 4
    for (int d = 0; d < DSZ; ++d) {
        float w = wp[d * HSZ];
        #pragma unroll
        for (int bb = 0; bb < BQ; ++bb) acc[bb] += xk[bb][d] * w;
    }
    #pragma unroll
    for (int bb = 0; bb < BQ; ++bb)
        g_x1[((size_t)bb * NP + n) * HSZ + h] = fmaxf(acc[bb], 0.f);
}

// ---------------- 7. LN stats over (N,H) per batch ----------------
__global__ void k_ln() {
    int b = blockIdx.x;
    const float* p = &g_x1[(size_t)b * NP * HSZ];
    double s = 0.0, q = 0.0;
    for (int i = threadIdx.x; i < NP * HSZ; i += 512) {
        float v = p[i]; s += v; q += (double)v * v;
    }
    __shared__ double rs[512], rq[512];
    rs[threadIdx.x] = s; rq[threadIdx.x] = q; __syncthreads();
    for (int st = 256; st > 0; st >>= 1) {
        if (threadIdx.x < st) { rs[threadIdx.x] += rs[threadIdx.x + st]; rq[threadIdx.x] += rq[threadIdx.x + st]; }
        __syncthreads();
    }
    if (threadIdx.x == 0) {
        double mu  = rs[0] / (double)NHB;
        double var = rq[0] / (double)NHB - mu * mu;
        g_mu[b]   = (float)mu;
        g_rstd[b] = (float)(1.0 / sqrt(var + 1e-8));
    }
}

// ---------------- 8. column sums of Wxabs ----------------
__global__ void k_wcs(const float* __restrict__ W) {
    int k = threadIdx.x;
    float s = 0.f;
    for (int h = 0; h < HSZ; ++h) s += W[h * HSZ + k];
    g_wcs[k] = s;
}

// ---------------- 9. adp = LN(x1) @ Wxabs via tf32x3 mma (LN fused) ----------
#define APITCH 36
#define ARAW   (128*APITCH)
#define ADP_SMEM ((2*ARAW + 4*ARAW)*4)   // rawA dbuf + Wt[4 chunks] = 110592 B

__global__ void __launch_bounds__(512) k_adp(const float* __restrict__ W) {
    extern __shared__ float psm[];
    float* rawA = psm;                 // [2][ARAW]
    float* Wt   = psm + 2 * ARAW;      // [4][128*APITCH]: Wt[c][k][hh] = W[c*32+hh][k]
    int b = blockIdx.z, n0 = blockIdx.x * 128;
    int tid = threadIdx.x;
    int lane = tid & 31, w = tid >> 5;
    int wm = (w >> 2) * 32;
    int wn = (w & 3) * 32;

    const float* Ag = &g_x1[((size_t)b * NP + n0) * HSZ];

    // transpose-fill W into Wt (coalesced reads; reused across all 4 chunks)
    for (int idx = tid; idx < HSZ * HSZ; idx += 512) {
        int h = idx >> 7, k = idx & 127;
        Wt[(h >> 5) * ARAW + k * APITCH + (h & 31)] = W[h * HSZ + k];
    }

    float acc[2][4][4];
    #pragma unroll
    for (int mi = 0; mi < 2; ++mi)
        #pragma unroll
        for (int ni = 0; ni < 4; ++ni)
            #pragma unroll
            for (int q = 0; q < 4; ++q) acc[mi][ni][q] = 0.f;

    // prefetch A h-chunk 0
    #pragma unroll
    for (int q = 0; q < 2; ++q) {
        int idx = tid + q * 512;
        int r = idx >> 3, c = (idx & 7) * 4;
        cp16(&rawA[r * APITCH + c], &Ag[(size_t)r * HSZ + c]);
    }
    cp_commit();

    for (int kt = 0; kt < 4; ++kt) {
        int buf = kt & 1;
        if (kt + 1 < 4) {
            int k0 = (kt + 1) * 32;
            float* dA = rawA + (buf ^ 1) * ARAW;
            #pragma unroll
            for (int q = 0; q < 2; ++q) {
                int idx = tid + q * 512;
                int r = idx >> 3, c = (idx & 7) * 4;
                cp16(&dA[r * APITCH + c], &Ag[(size_t)r * HSZ + k0 + c]);
            }
            cp_commit();
            cp_wait<1>();
        } else {
            cp_wait<0>();
        }
        __syncthreads();   // also covers the one-time Wt fill at kt==0

        const float* cA = rawA + buf * ARAW;
        const float* cW = Wt + kt * ARAW;
        #pragma unroll
        for (int ks = 0; ks < 4; ++ks) {
            int kc = ks * 8 + (lane & 3);
            uint32_t AhF[2][4], AlF[2][4], BhF[4][2], BlF[4][2];
            #pragma unroll
            for (int mi = 0; mi < 2; ++mi) {
                int o = (wm + mi * 16 + (lane >> 2)) * APITCH + kc;
                float h, l;
                msplit(cA[o],                  h, l); AhF[mi][0] = __float_as_uint(h); AlF[mi][0] = __float_as_uint(l);
                msplit(cA[o + 8 * APITCH],     h, l); AhF[mi][1] = __float_as_uint(h); AlF[mi][1] = __float_as_uint(l);
                msplit(cA[o + 4],              h, l); AhF[mi][2] = __float_as_uint(h); AlF[mi][2] = __float_as_uint(l);
                msplit(cA[o + 8 * APITCH + 4], h, l); AhF[mi][3] = __float_as_uint(h); AlF[mi][3] = __float_as_uint(l);
            }
            #pragma unroll
            for (int ni = 0; ni < 4; ++ni) {
                int o = (wn + ni * 8 + (lane >> 2)) * APITCH + kc;
                float h, l;
                msplit(cW[o],     h, l); BhF[ni][0] = __float_as_uint(h); BlF[ni][0] = __float_as_uint(l);
                msplit(cW[o + 4], h, l); BhF[ni][1] = __float_as_uint(h); BlF[ni][1] = __float_as_uint(l);
            }
            #pragma unroll
            for (int mi = 0; mi < 2; ++mi)
                #pragma unroll
                for (int ni = 0; ni < 4; ++ni) {
                    mma_tf32(acc[mi][ni], AhF[mi], BhF[ni]);
                    mma_tf32(acc[mi][ni], AhF[mi], BlF[ni]);
                    mma_tf32(acc[mi][ni], AlF[mi], BhF[ni]);
                }
        }
        __syncthreads();
    }

    // epilogue: LN transform + store (padding rows n>=NSZ stay zero)
    float mu = g_mu[b], rstd = g_rstd[b];
    #pragma unroll
    for (int mi = 0; mi < 2; ++mi) {
        int r = n0 + wm + mi * 16 + (lane >> 2);
        #pragma unroll
        for (int ni = 0; ni < 4; ++ni) {
            int c = wn + ni * 8 + ((lane & 3) << 1);
            float* C = acc[mi][ni];
            float w0 = g_wcs[c], w1 = g_wcs[c + 1];
            if (r < NSZ) {
                float* p = &g_adp[((size_t)b * NP + r) * HSZ];
                p[c]     = rstd * (C[0] - mu * w0);
                p[c + 1] = rstd * (C[1] - mu * w1);
            }
            if (r + 8 < NSZ) {
                float* p = &g_adp[((size_t)b * NP + r + 8) * HSZ];
                p[c]     = rstd * (C[2] - mu * w0);
                p[c + 1] = rstd * (C[3] - mu * w1);
            }
        }
    }
}

// ---------------- 10. adj: tf32x3 mma, raw cp.async dbuf, frag-time split ----
#define SPITCH 36
#define RAWSZ  (128*SPITCH)
#define ADJ_SMEM (4*RAWSZ*4)   // rawA[2] + rawB[2] = 73728 bytes

__global__ void __launch_bounds__(512) k_adj() {
    extern __shared__ float sm[];
    float* rawA = sm;
    float* rawB = sm + 2 * RAWSZ;
    int b  = blockIdx.z;
    int n0 = blockIdx.y * 128;
    int m0 = blockIdx.x * 128;
    int tid = threadIdx.x;
    int lane = tid & 31, w = tid >> 5;
    int wm = (w >> 2) * 32;
    int wn = (w & 3) * 32;

    const float* Ag = &g_adp[((size_t)b * NP + n0) * HSZ];
    const float* Bg = &g_x1 [((size_t)b * NP + m0) * HSZ];

    float acc[2][4][4];
    #pragma unroll
    for (int mi = 0; mi < 2; ++mi)
        #pragma unroll
        for (int ni = 0; ni < 4; ++ni)
            #pragma unroll
            for (int q = 0; q < 4; ++q) acc[mi][ni][q] = 0.f;

    #pragma unroll
    for (int q = 0; q < 2; ++q) {
        int idx = tid + q * 512;
        int r = idx >> 3, c = (idx & 7) * 4;
        cp16(&rawA[r * SPITCH + c], &Ag[(size_t)r * HSZ + c]);
        cp16(&rawB[r * SPITCH + c], &Bg[(size_t)r * HSZ + c]);
    }
    cp_commit();

    for (int kt = 0; kt < 4; ++kt) {
        int buf = kt & 1;
        if (kt + 1 < 4) {
            int k0 = (kt + 1) * 32;
            float* dA = rawA + (buf ^ 1) * RAWSZ;
            float* dB = rawB + (buf ^ 1) * RAWSZ;
            #pragma unroll
            for (int q = 0; q < 2; ++q) {
                int idx = tid + q * 512;
                int r = idx >> 3, c = (idx & 7) * 4;
                cp16(&dA[r * SPITCH + c], &Ag[(size_t)r * HSZ + k0 + c]);
                cp16(&dB[r * SPITCH + c], &Bg[(size_t)r * HSZ + k0 + c]);
            }
            cp_commit();
            cp_wait<1>();
        } else {
            cp_wait<0>();
        }
        __syncthreads();

        const float* cA = rawA + buf * RAWSZ;
        const float* cB = rawB + buf * RAWSZ;
        #pragma unroll
        for (int ks = 0; ks < 4; ++ks) {
            int kc = ks * 8 + (lane & 3);
            uint32_t AhF[2][4], AlF[2][4], BhF[4][2], BlF[4][2];
            #pragma unroll
            for (int mi = 0; mi < 2; ++mi) {
                int o = (wm + mi * 16 + (lane >> 2)) * SPITCH + kc;
                float h, l;
                msplit(cA[o],                  h, l); AhF[mi][0] = __float_as_uint(h); AlF[mi][0] = __float_as_uint(l);
                msplit(cA[o + 8 * SPITCH],     h, l); AhF[mi][1] = __float_as_uint(h); AlF[mi][1] = __float_as_uint(l);
                msplit(cA[o + 4],              h, l); AhF[mi][2] = __float_as_uint(h); AlF[mi][2] = __float_as_uint(l);
                msplit(cA[o + 8 * SPITCH + 4], h, l); AhF[mi][3] = __float_as_uint(h); AlF[mi][3] = __float_as_uint(l);
            }
            #pragma unroll
            for (int ni = 0; ni < 4; ++ni) {
                int o = (wn + ni * 8 + (lane >> 2)) * SPITCH + kc;
                float h, l;
                msplit(cB[o],     h, l); BhF[ni][0] = __float_as_uint(h); BlF[ni][0] = __float_as_uint(l);
                msplit(cB[o + 4], h, l); BhF[ni][1] = __float_as_uint(h); BlF[ni][1] = __float_as_uint(l);
            }
            #pragma unroll
            for (int mi = 0; mi < 2; ++mi)
                #pragma unroll
                for (int ni = 0; ni < 4; ++ni) {
                    mma_tf32(acc[mi][ni], AhF[mi], BhF[ni]);
                    mma_tf32(acc[mi][ni], AhF[mi], BlF[ni]);
                    mma_tf32(acc[mi][ni], AlF[mi], BhF[ni]);
                }
        }
        __syncthreads();
    }

    float* abase = &g_adj[(size_t)b * NSZ * NSZ];
    #pragma unroll
    for (int mi = 0; mi < 2; ++mi) {
        int r = n0 + wm + mi * 16 + (lane >> 2);
        #pragma unroll
        for (int ni = 0; ni < 4; ++ni) {
            int c = m0 + wn + ni * 8 + ((lane & 3) << 1);
            float* C = acc[mi][ni];
            if (r < NSZ) {
                float* row = abase + (size_t)r * NSZ;
                if (c     < NSZ) row[c]     = fmaxf(C[0], 0.f);
                if (c + 1 < NSZ) row[c + 1] = fmaxf(C[1], 0.f);
            }
            if (r + 8 < NSZ) {
                float* row = abase + (size_t)(r + 8) * NSZ;
                if (c     < NSZ) row[c]     = fmaxf(C[2], 0.f);
                if (c + 1 < NSZ) row[c + 1] = fmaxf(C[3], 0.f);
            }
        }
    }
}

// ---------------- 11. per-row exact radix-select top-20 + softmax ------------
#define MAXEQ 64
__global__ void __launch_bounds__(256) k_topk(float* __restrict__ out) {
    int n = blockIdx.x, b = blockIdx.y, tid = threadIdx.x;
    const float* row = &g_adj[((size_t)b * NSZ + n) * NSZ];

    unsigned v[8];
    #pragma unroll
    for (int j = 0; j < 8; ++j) {
        int m = tid + j * 256;
        v[j] = (m < NSZ) ? __float_as_uint(row[m]) : 0u;
    }

    __shared__ unsigned hist[256];
    __shared__ unsigned s_bin, s_kneed, s_maxb;
    __shared__ unsigned warpmax[8];
    __shared__ float s_red[256];
    __shared__ float sD;
    __shared__ int eqn, eqselN;
    __shared__ int eqlist[MAXEQ];
    __shared__ int eqsel[KTOP];

    unsigned mx = v[0];
    #pragma unroll
    for (int j = 1; j < 8; ++j) mx = max(mx, v[j]);
    #pragma unroll
    for (int s = 16; s; s >>= 1) mx = max(mx, __shfl_xor_sync(0xffffffffu, mx, s));
    if (!(tid & 31)) warpmax[tid >> 5] = mx;
    if (tid == 0) eqn = 0;
    __syncthreads();
    if (tid == 0) {
        unsigned m2 = warpmax[0];
        #pragma unroll
        for (int i = 1; i < 8; ++i) m2 = max(m2, warpmax[i]);
        s_maxb = m2;
    }

    unsigned prefix = 0, mask = 0, Kneed = KTOP;
    #pragma unroll
    for (int pass = 0; pass < 4; ++pass) {
        int shift = 24 - pass * 8;
        __syncthreads();
        hist[tid] = 0;
        __syncthreads();
        #pragma unroll
        for (int j = 0; j < 8; ++j) {
            int m = tid + j * 256;
            if (m < NSZ && (v[j] & mask) == prefix)
                atomicAdd(&hist[(v[j] >> shift) & 255], 1u);
        }
        __syncthreads();
        if (tid < 32) {
            unsigned s = 0;
            #pragma unroll
            for (int k = 0; k < 8; ++k) s += hist[tid * 8 + k];
            unsigned suf = s;
            #pragma unroll
            for (int d = 1; d < 32; d <<= 1) {
                unsigned o = __shfl_down_sync(0xffffffffu, suf, d);
                if (tid + d < 32) suf += o;
            }
            unsigned above = suf - s;
            if (above < Kneed && above + s >= Kneed) {
                unsigned cum = above;
                for (int k = 7; k >= 0; --k) {
                    unsigned h = hist[tid * 8 + k];
                    if (cum + h >= Kneed) { s_bin = tid * 8 + k; s_kneed = Kneed - cum; break; }
                    cum += h;
                }
            }
        }
        __syncthreads();
        prefix |= s_bin << shift;
        mask   |= 0xFFu << shift;
        Kneed   = s_kneed;
    }
    unsigned T = prefix;
    float Tf   = __uint_as_float(T);
    float vmax = __uint_as_float(s_maxb);

    #pragma unroll
    for (int j = 0; j < 8; ++j) {
        int m = tid + j * 256;
        if (m < NSZ && v[j] == T) {
            int p = atomicAdd(&eqn, 1);
            if (p < MAXEQ) eqlist[p] = m;
        }
    }
    __syncthreads();
    if (tid == 0) {
        int cnt = eqn < MAXEQ ? eqn : MAXEQ;
        int need = (int)Kneed; if (need > KTOP) need = KTOP;
        int sel = 0;
        for (int a = 0; a < need && a < cnt; ++a) {
            int bi = a;
            for (int c = a + 1; c < cnt; ++c) if (eqlist[c] < eqlist[bi]) bi = c;
            int t2 = eqlist[a]; eqlist[a] = eqlist[bi]; eqlist[bi] = t2;
            eqsel[a] = eqlist[a]; ++sel;
        }
        eqselN = sel;
    }
    __syncthreads();

    float s = 0.f;
    #pragma unroll
    for (int j = 0; j < 8; ++j) {
        int m = tid + j * 256;
        if (m < NSZ && v[j] > T) s += expf(__uint_as_float(v[j]) - vmax);
    }
    s_red[tid] = s; __syncthreads();
    for (int st = 128; st; st >>= 1) {
        if (tid < st) s_red[tid] += s_red[tid + st];
        __syncthreads();
    }
    if (tid == 0)
        sD = s_red[0] + (float)eqselN * expf(Tf - vmax)
           + (float)(NSZ - KTOP) * expf(-vmax);
    __syncthreads();

    float D = sD;
    float base = expf(-vmax) / D;
    float* orow = &out[((size_t)b * NSZ + n) * NSZ];
    float4 b4 = make_float4(base, base, base, base);
    for (int i = tid; i < NSZ / 4; i += 256) ((float4*)orow)[i] = b4;
    __syncthreads();
    int nEq = eqselN;
    #pragma unroll
    for (int j = 0; j < 8; ++j) {
        int m = tid + j * 256;
        if (m < NSZ) {
            if (v[j] > T) {
                orow[m] = expf(__uint_as_float(v[j]) - vmax) / D;
            } else if (v[j] == T) {
                for (int a = 0; a < nEq; ++a)
                    if (eqsel[a] == m) { orow[m] = expf(Tf - vmax) / D; break; }
            }
        }
    }
}

// ---------------- launch ----------------
extern "C" void kernel_launch(void* const* d_in, const int* in_sizes, int n_in,
                              void* d_out, int out_size) {
    const float* x     = (const float*)d_in[0];
    const float* Ex    = (const float*)d_in[1];
    const float* nodes = (const float*)d_in[2];
    const float* Wd    = (const float*)d_in[3];
    const float* W     = (const float*)d_in[4];
    float* out = (float*)d_out;

    cudaFuncSetAttribute(k_xe,  cudaFuncAttributeMaxDynamicSharedMemorySize, XE_SMEM);
    cudaFuncSetAttribute(k_adp, cudaFuncAttributeMaxDynamicSharedMemorySize, ADP_SMEM);
    cudaFuncSetAttribute(k_adj, cudaFuncAttributeMaxDynamicSharedMemorySize, ADJ_SMEM);

    k_basis<<<(FLSZ * TSZ + 255) / 256, 256>>>();
    k_dummy<<<1, 32>>>();
    k_dummy<<<1, 32>>>();                       // k_dft stays at ncu capture index
    k_dft  <<<dim3(16, 5, BQ), 256>>>(x);
    k_invn <<<dim3(FLSZ, BQ), 256>>>();
    k_invf <<<dim3((NSZ + 63) / 64, BQ), 256>>>();
    k_xe   <<<dim3(16, 1, BQ), 512, XE_SMEM>>>(Ex);
    k_x1   <<<NSZ, 128>>>(nodes, Wd);
    k_ln   <<<BQ, 512>>>();
    k_wcs  <<<1, 128>>>(W);
    k_adp  <<<dim3(16, 1, BQ), 512, ADP_SMEM>>>(W);
    k_adj  <<<dim3(16, 16, BQ), 512, ADJ_SMEM>>>();
    k_topk <<<dim3(NSZ, BQ), 256>>>(out);
}

// round 11
// speedup vs baseline: 2.6201x; 1.3877x over previous
#include <cuda_runtime.h>
#include <math.h>
#include <stdint.h>

#define BQ    8
#define TSZ   288
#define NSZ   2000
#define NP    2048
#define FLSZ  145
#define FPAD  160
#define ESZ   128
#define IDSZ  16
#define DSZ   144
#define HSZ   128
#define KTOP  20
#define NHB   (NSZ*HSZ)

// ---------------- scratch (__device__ globals: allocation-free, zero-init) ----
__device__ float g_cos[FPAD*TSZ];
__device__ float g_sin[FPAD*TSZ];
__device__ float g_xf  [BQ*FLSZ*NSZ];
__device__ float g_invn[BQ*FLSZ];
__device__ float g_invf[BQ*NSZ];
__device__ float g_xe  [BQ*NSZ*ESZ];
__device__ float g_x1  [(size_t)BQ*NP*HSZ];
__device__ float g_mu  [BQ];
__device__ float g_rstd[BQ];
__device__ float g_wcs [HSZ];
__device__ double g_lps[BQ*8];
__device__ double g_lpq[BQ*8];
__device__ float g_adp [(size_t)BQ*NP*HSZ];
__device__ float g_adj [(size_t)BQ*NSZ*NSZ];

// ---------------- helpers ----------------
__device__ __forceinline__ void msplit(float x, float& hi, float& lo) {
    uint32_t hb = __float_as_uint(x) & 0xFFFFE000u;
    float hf = __uint_as_float(hb);
    hi = hf; lo = x - hf;
}
__device__ __forceinline__ void mma_tf32(float* c, const uint32_t* a, const uint32_t* b) {
    asm volatile(
        "mma.sync.aligned.m16n8k8.row.col.f32.tf32.tf32.f32 "
        "{%0,%1,%2,%3}, {%4,%5,%6,%7}, {%8,%9}, {%0,%1,%2,%3};"
        : "+f"(c[0]), "+f"(c[1]), "+f"(c[2]), "+f"(c[3])
        : "r"(a[0]), "r"(a[1]), "r"(a[2]), "r"(a[3]), "r"(b[0]), "r"(b[1]));
}
__device__ __forceinline__ void cp16(void* smem_dst, const void* gmem_src) {
    unsigned sa = (unsigned)__cvta_generic_to_shared(smem_dst);
    asm volatile("cp.async.ca.shared.global [%0], [%1], 16;\n" :: "r"(sa), "l"(gmem_src));
}
__device__ __forceinline__ void cp_commit() { asm volatile("cp.async.commit_group;\n"); }
template<int N> __device__ __forceinline__ void cp_wait() {
    asm volatile("cp.async.wait_group %0;\n" :: "n"(N));
}

__global__ void k_dummy() {}

// ---------------- 1. DFT basis (exact integer phase reduction) ---------------
__global__ void k_basis() {
    int i = blockIdx.x * blockDim.x + threadIdx.x;
    if (i < FLSZ * TSZ) {
        int f = i / TSZ, t = i % TSZ;
        int m = (f * t) % TSZ;
        float ang = (float)((double)m * 6.283185307179586 / (double)TSZ);
        int o = f * TSZ + t;
        g_cos[o] = cosf(ang);
        g_sin[o] = sinf(ang);
    }
}

// ---------------- 2. |rfft| via tf32x3 mma, raw smem, frag-time split --------
#define XP 33
#define BP 36
__global__ void __launch_bounds__(256) k_dft(const float* __restrict__ x) {
    __shared__ float Xs[128 * XP];
    __shared__ float Cs[32 * BP];
    __shared__ float Ss[32 * BP];
    int b  = blockIdx.z;
    int n0 = blockIdx.x * 128;
    int f0 = blockIdx.y * 32;
    int tid = threadIdx.x;
    int lane = tid & 31, w = tid >> 5;
    int wm = (w >> 2) * 16;
    int wn = (w & 3) * 32;

    float accR[4][4], accI[4][4];
    #pragma unroll
    for (int ni = 0; ni < 4; ++ni)
        #pragma unroll
        for (int q = 0; q < 4; ++q) { accR[ni][q] = 0.f; accI[ni][q] = 0.f; }

    for (int t0 = 0; t0 < TSZ; t0 += 32) {
        __syncthreads();
        #pragma unroll
        for (int q = 0; q < 2; ++q) {
            int idx = tid + q * 256;
            int a = idx >> 8, rem = idx & 255;
            int r = rem >> 3, c = rem & 7;
            float* dst = a ? Ss : Cs;
            const float* src = a ? g_sin : g_cos;
            cp16(dst + r * BP + c * 4, src + (f0 + r) * TSZ + t0 + c * 4);
        }
        cp_commit();
        #pragma unroll
        for (int tj = 0; tj < 4; ++tj) {
            int t = w * 4 + tj;
            #pragma unroll
            for (int ng = 0; ng < 4; ++ng) {
                int nl = ng * 32 + lane;
                int gn = n0 + nl;
                Xs[nl * XP + t] = (gn < NSZ) ? x[((size_t)b * TSZ + t0 + t) * NSZ + gn] : 0.f;
            }
        }
        cp_wait<0>();
        __syncthreads();

        #pragma unroll
        for (int ks = 0; ks < 4; ++ks) {
            int kc = ks * 8 + (lane & 3);
            int oa = (wm + (lane >> 2)) * BP + kc;
            uint32_t ChF[4], ClF[4], ShF[4], SlF[4];
            {
                float h, l;
                msplit(Cs[oa],              h, l); ChF[0] = __float_as_uint(h); ClF[0] = __float_as_uint(l);
                msplit(Cs[oa + 8 * BP],     h, l); ChF[1] = __float_as_uint(h); ClF[1] = __float_as_uint(l);
                msplit(Cs[oa + 4],          h, l); ChF[2] = __float_as_uint(h); ClF[2] = __float_as_uint(l);
                msplit(Cs[oa + 8 * BP + 4], h, l); ChF[3] = __float_as_uint(h); ClF[3] = __float_as_uint(l);
                msplit(Ss[oa],              h, l); ShF[0] = __float_as_uint(h); SlF[0] = __float_as_uint(l);
                msplit(Ss[oa + 8 * BP],     h, l); ShF[1] = __float_as_uint(h); SlF[1] = __float_as_uint(l);
                msplit(Ss[oa + 4],          h, l); ShF[2] = __float_as_uint(h); SlF[2] = __float_as_uint(l);
                msplit(Ss[oa + 8 * BP + 4], h, l); ShF[3] = __float_as_uint(h); SlF[3] = __float_as_uint(l);
            }
            #pragma unroll
            for (int ni = 0; ni < 4; ++ni) {
                int ob = (wn + ni * 8 + (lane >> 2)) * XP + kc;
                float h0, l0, h1, l1;
                msplit(Xs[ob],     h0, l0);
                msplit(Xs[ob + 4], h1, l1);
                uint32_t XhF[2] = {__float_as_uint(h0), __float_as_uint(h1)};
                uint32_t XlF[2] = {__float_as_uint(l0), __float_as_uint(l1)};
                mma_tf32(accR[ni], ChF, XhF);
                mma_tf32(accR[ni], ChF, XlF);
                mma_tf32(accR[ni], ClF, XhF);
                mma_tf32(accI[ni], ShF, XhF);
                mma_tf32(accI[ni], ShF, XlF);
                mma_tf32(accI[ni], SlF, XhF);
            }
        }
    }

    int fr = f0 + wm + (lane >> 2);
    #pragma unroll
    for (int ni = 0; ni < 4; ++ni) {
        int cN = n0 + wn + ni * 8 + ((lane & 3) << 1);
        if (fr < FLSZ) {
            float* p = &g_xf[(b * FLSZ + fr) * NSZ];
            if (cN     < NSZ) p[cN]     = sqrtf(accR[ni][0]*accR[ni][0] + accI[ni][0]*accI[ni][0]);
            if (cN + 1 < NSZ) p[cN + 1] = sqrtf(accR[ni][1]*accR[ni][1] + accI[ni][1]*accI[ni][1]);
        }
        if (fr + 8 < FLSZ) {
            float* p = &g_xf[(b * FLSZ + fr + 8) * NSZ];
            if (cN     < NSZ) p[cN]     = sqrtf(accR[ni][2]*accR[ni][2] + accI[ni][2]*accI[ni][2]);
            if (cN + 1 < NSZ) p[cN + 1] = sqrtf(accR[ni][3]*accR[ni][3] + accI[ni][3]*accI[ni][3]);
        }
    }
}

// ---------------- 3. norm over nodes (axis=1) ----------------
__global__ void k_invn() {
    int f = blockIdx.x, b = blockIdx.y;
    const float* p = &g_xf[(b * FLSZ + f) * NSZ];
    float s = 0.f;
    for (int i = threadIdx.x; i < NSZ; i += 256) { float v = p[i]; s += v * v; }
    __shared__ float red[256];
    red[threadIdx.x] = s; __syncthreads();
    for (int st = 128; st > 0; st >>= 1) {
        if (threadIdx.x < st) red[threadIdx.x] += red[threadIdx.x + st];
        __syncthreads();
    }
    if (threadIdx.x == 0)
        g_invn[b * FLSZ + f] = 1.f / fmaxf(sqrtf(red[0]), 1e-12f);
}

// ---------------- 4. norm over freq (axis=2) ----------------
__global__ void k_invf() {
    int b = blockIdx.y;
    int nl = threadIdx.x & 63;
    int n  = blockIdx.x * 64 + nl;
    int fp = threadIdx.x >> 6;
    float s = 0.f;
    if (n < NSZ)
        for (int f = fp; f < FLSZ; f += 4) {
            float v = g_xf[(b * FLSZ + f) * NSZ + n] * g_invn[b * FLSZ + f];
            s += v * v;
        }
    __shared__ float red[256];
    red[threadIdx.x] = s; __syncthreads();
    if (threadIdx.x < 64 && n < NSZ) {
        s = red[nl] + red[nl + 64] + red[nl + 128] + red[nl + 192];
        g_invf[b * NSZ + n] = 1.f / fmaxf(sqrtf(s), 1e-12f);
    }
}

// ---------------- 5. xe = normalized(xf) @ Ex via tf32x3 mma -----------------
#define XE_SMEM (4*128*BP*4)
__global__ void __launch_bounds__(512) k_xe(const float* __restrict__ Ex) {
    extern __shared__ float xsm[];
    float* Ah = xsm;
    float* Al = Ah + 128 * BP;
    float* Bh = Al + 128 * BP;
    float* Bl = Bh + 128 * BP;
    int b = blockIdx.z, n0 = blockIdx.x * 128;
    int tid = threadIdx.x;
    int lane = tid & 31, w = tid >> 5;
    int wm = (w >> 2) * 32;
    int wn = (w & 3) * 32;

    float acc[2][4][4];
    #pragma unroll
    for (int mi = 0; mi < 2; ++mi)
        #pragma unroll
        for (int ni = 0; ni < 4; ++ni)
            #pragma unroll
            for (int q = 0; q < 4; ++q) acc[mi][ni][q] = 0.f;

    for (int f0 = 0; f0 < FPAD; f0 += 32) {
        __syncthreads();
        #pragma unroll
        for (int q = 0; q < 8; ++q) {
            int idx = tid + q * 512;
            int fc = idx >> 7, nl = idx & 127;
            int f = f0 + fc, gn = n0 + nl;
            float val = 0.f;
            if (f < FLSZ && gn < NSZ)
                val = g_xf[(b * FLSZ + f) * NSZ + gn] * g_invn[b * FLSZ + f];
            float h, l; msplit(val, h, l);
            Ah[nl * BP + fc] = h; Al[nl * BP + fc] = l;
        }
        #pragma unroll
        for (int q = 0; q < 8; ++q) {
            int idx = tid + q * 512;
            int fc = idx >> 7, e = idx & 127;
            int f = f0 + fc;
            float val = (f < FLSZ) ? Ex[f * ESZ + e] : 0.f;
            float h, l; msplit(val, h, l);
            Bh[e * BP + fc] = h; Bl[e * BP + fc] = l;
        }
        __syncthreads();
        #pragma unroll
        for (int ks = 0; ks < 4; ++ks) {
            int kc = ks * 8 + (lane & 3);
            uint32_t AhF[2][4], AlF[2][4], BhF[4][2], BlF[4][2];
            #pragma unroll
            for (int mi = 0; mi < 2; ++mi) {
                int o = (wm + mi * 16 + (lane >> 2)) * BP + kc;
                AhF[mi][0] = __float_as_uint(Ah[o]);     AhF[mi][1] = __float_as_uint(Ah[o + 8 * BP]);
                AhF[mi][2] = __float_as_uint(Ah[o + 4]); AhF[mi][3] = __float_as_uint(Ah[o + 8 * BP + 4]);
                AlF[mi][0] = __float_as_uint(Al[o]);     AlF[mi][1] = __float_as_uint(Al[o + 8 * BP]);
                AlF[mi][2] = __float_as_uint(Al[o + 4]); AlF[mi][3] = __float_as_uint(Al[o + 8 * BP + 4]);
            }
            #pragma unroll
            for (int ni = 0; ni < 4; ++ni) {
                int o = (wn + ni * 8 + (lane >> 2)) * BP + kc;
                BhF[ni][0] = __float_as_uint(Bh[o]); BhF[ni][1] = __float_as_uint(Bh[o + 4]);
                BlF[ni][0] = __float_as_uint(Bl[o]); BlF[ni][1] = __float_as_uint(Bl[o + 4]);
            }
            #pragma unroll
            for (int mi = 0; mi < 2; ++mi)
                #pragma unroll
                for (int ni = 0; ni < 4; ++ni) {
                    mma_tf32(acc[mi][ni], AhF[mi], BhF[ni]);
                    mma_tf32(acc[mi][ni], AhF[mi], BlF[ni]);
                    mma_tf32(acc[mi][ni], AlF[mi], BhF[ni]);
                }
        }
    }

    #pragma unroll
    for (int mi = 0; mi < 2; ++mi) {
        int r0 = n0 + wm + mi * 16 + (lane >> 2);
        #pragma unroll
        for (int ni = 0; ni < 4; ++ni) {
            int c = wn + ni * 8 + ((lane & 3) << 1);
            float* C = acc[mi][ni];
            if (r0 < NSZ) {
                float sc = g_invf[b * NSZ + r0];
                float* p = &g_xe[((size_t)b * NSZ + r0) * ESZ];
                p[c] = C[0] * sc; p[c + 1] = C[1] * sc;
            }
            if (r0 + 8 < NSZ) {
                float sc = g_invf[b * NSZ + r0 + 8];
                float* p = &g_xe[((size_t)b * NSZ + r0 + 8) * ESZ];
                p[c] = C[2] * sc; p[c + 1] = C[3] * sc;
            }
        }
    }
}

// ---------------- 6. x1 = relu(per-node [8,144]@[144,128]) -------------------
__global__ void k_x1(const float* __restrict__ nodes, const float* __restrict__ Wd) {
    __shared__ float xk[BQ][DSZ];
    int n = blockIdx.x;
    int h = threadIdx.x;
    for (int idx = h; idx < BQ * ESZ; idx += 128) {
        int bb = idx >> 7, e = idx & 127;
        xk[bb][e] = g_xe[(bb * NSZ + n) * ESZ + e];
    }
    for (int idx = h; idx < BQ * IDSZ; idx += 128) {
        int bb = idx >> 4, i2 = idx & 15;
        xk[bb][ESZ + i2] = nodes[n * IDSZ + i2];
    }
    __syncthreads();
    float acc[BQ] = {};
    const float* wp = &Wd[(size_t)n * DSZ * HSZ + h];
    #pragma unroll 4
    for (int d = 0; d < DSZ; ++d) {
        float w = wp[d * HSZ];
        #pragma unroll
        for (int bb = 0; bb < BQ; ++bb) acc[bb] += xk[bb][d] * w;
    }
    #pragma unroll
    for (int bb = 0; bb < BQ; ++bb)
        g_x1[((size_t)bb * NP + n) * HSZ + h] = fmaxf(acc[bb], 0.f);
}

// ---------------- 7. LN stats: 2-stage (64 partial blocks + finalize) --------
__global__ void k_ln1() {
    int chunk = blockIdx.x, b = blockIdx.y;
    const int CH = NP * HSZ / 8;   // 32768
    const float* p = &g_x1[(size_t)b * NP * HSZ + (size_t)chunk * CH];
    double s = 0.0, q = 0.0;
    for (int i = threadIdx.x; i < CH; i += 256) {
        float v = p[i]; s += v; q += (double)v * v;
    }
    __shared__ double rs[256], rq[256];
    rs[threadIdx.x] = s; rq[threadIdx.x] = q; __syncthreads();
    for (int st = 128; st > 0; st >>= 1) {
        if (threadIdx.x < st) { rs[threadIdx.x] += rs[threadIdx.x + st]; rq[threadIdx.x] += rq[threadIdx.x + st]; }
        __syncthreads();
    }
    if (threadIdx.x == 0) {
        g_lps[b * 8 + chunk] = rs[0];
        g_lpq[b * 8 + chunk] = rq[0];
    }
}
__global__ void k_ln2() {
    int b = threadIdx.x;
    if (b < BQ) {
        double s = 0.0, q = 0.0;
        for (int c = 0; c < 8; ++c) { s += g_lps[b * 8 + c]; q += g_lpq[b * 8 + c]; }
        double mu  = s / (double)NHB;
        double var = q / (double)NHB - mu * mu;
        g_mu[b]   = (float)mu;
        g_rstd[b] = (float)(1.0 / sqrt(var + 1e-8));
    }
}

// ---------------- 8. column sums of Wxabs ----------------
__global__ void k_wcs(const float* __restrict__ W) {
    int k = threadIdx.x;
    float s = 0.f;
    for (int h = 0; h < HSZ; ++h) s += W[h * HSZ + k];
    g_wcs[k] = s;
}

// ---------------- 9. adp = LN(x1) @ Wxabs via tf32x3 mma (LN fused) ----------
#define APITCH 36
#define ARAW   (128*APITCH)
#define ADP_SMEM ((2*ARAW + 4*ARAW)*4)

__global__ void __launch_bounds__(512) k_adp(const float* __restrict__ W) {
    extern __shared__ float psm[];
    float* rawA = psm;
    float* Wt   = psm + 2 * ARAW;
    int b = blockIdx.z, n0 = blockIdx.x * 128;
    int tid = threadIdx.x;
    int lane = tid & 31, w = tid >> 5;
    int wm = (w >> 2) * 32;
    int wn = (w & 3) * 32;

    const float* Ag = &g_x1[((size_t)b * NP + n0) * HSZ];

    for (int idx = tid; idx < HSZ * HSZ; idx += 512) {
        int h = idx >> 7, k = idx & 127;
        Wt[(h >> 5) * ARAW + k * APITCH + (h & 31)] = W[h * HSZ + k];
    }

    float acc[2][4][4];
    #pragma unroll
    for (int mi = 0; mi < 2; ++mi)
        #pragma unroll
        for (int ni = 0; ni < 4; ++ni)
            #pragma unroll
            for (int q = 0; q < 4; ++q) acc[mi][ni][q] = 0.f;

    #pragma unroll
    for (int q = 0; q < 2; ++q) {
        int idx = tid + q * 512;
        int r = idx >> 3, c = (idx & 7) * 4;
        cp16(&rawA[r * APITCH + c], &Ag[(size_t)r * HSZ + c]);
    }
    cp_commit();

    for (int kt = 0; kt < 4; ++kt) {
        int buf = kt & 1;
        if (kt + 1 < 4) {
            int k0 = (kt + 1) * 32;
            float* dA = rawA + (buf ^ 1) * ARAW;
            #pragma unroll
            for (int q = 0; q < 2; ++q) {
                int idx = tid + q * 512;
                int r = idx >> 3, c = (idx & 7) * 4;
                cp16(&dA[r * APITCH + c], &Ag[(size_t)r * HSZ + k0 + c]);
            }
            cp_commit();
            cp_wait<1>();
        } else {
            cp_wait<0>();
        }
        __syncthreads();

        const float* cA = rawA + buf * ARAW;
        const float* cW = Wt + kt * ARAW;
        #pragma unroll
        for (int ks = 0; ks < 4; ++ks) {
            int kc = ks * 8 + (lane & 3);
            uint32_t AhF[2][4], AlF[2][4], BhF[4][2], BlF[4][2];
            #pragma unroll
            for (int mi = 0; mi < 2; ++mi) {
                int o = (wm + mi * 16 + (lane >> 2)) * APITCH + kc;
                float h, l;
                msplit(cA[o],                  h, l); AhF[mi][0] = __float_as_uint(h); AlF[mi][0] = __float_as_uint(l);
                msplit(cA[o + 8 * APITCH],     h, l); AhF[mi][1] = __float_as_uint(h); AlF[mi][1] = __float_as_uint(l);
                msplit(cA[o + 4],              h, l); AhF[mi][2] = __float_as_uint(h); AlF[mi][2] = __float_as_uint(l);
                msplit(cA[o + 8 * APITCH + 4], h, l); AhF[mi][3] = __float_as_uint(h); AlF[mi][3] = __float_as_uint(l);
            }
            #pragma unroll
            for (int ni = 0; ni < 4; ++ni) {
                int o = (wn + ni * 8 + (lane >> 2)) * APITCH + kc;
                float h, l;
                msplit(cW[o],     h, l); BhF[ni][0] = __float_as_uint(h); BlF[ni][0] = __float_as_uint(l);
                msplit(cW[o + 4], h, l); BhF[ni][1] = __float_as_uint(h); BlF[ni][1] = __float_as_uint(l);
            }
            #pragma unroll
            for (int mi = 0; mi < 2; ++mi)
                #pragma unroll
                for (int ni = 0; ni < 4; ++ni) {
                    mma_tf32(acc[mi][ni], AhF[mi], BhF[ni]);
                    mma_tf32(acc[mi][ni], AhF[mi], BlF[ni]);
                    mma_tf32(acc[mi][ni], AlF[mi], BhF[ni]);
                }
        }
        __syncthreads();
    }

    float mu = g_mu[b], rstd = g_rstd[b];
    #pragma unroll
    for (int mi = 0; mi < 2; ++mi) {
        int r = n0 + wm + mi * 16 + (lane >> 2);
        #pragma unroll
        for (int ni = 0; ni < 4; ++ni) {
            int c = wn + ni * 8 + ((lane & 3) << 1);
            float* C = acc[mi][ni];
            float w0 = g_wcs[c], w1 = g_wcs[c + 1];
            if (r < NSZ) {
                float* p = &g_adp[((size_t)b * NP + r) * HSZ];
                p[c]     = rstd * (C[0] - mu * w0);
                p[c + 1] = rstd * (C[1] - mu * w1);
            }
            if (r + 8 < NSZ) {
                float* p = &g_adp[((size_t)b * NP + r + 8) * HSZ];
                p[c]     = rstd * (C[2] - mu * w0);
                p[c + 1] = rstd * (C[3] - mu * w1);
            }
        }
    }
}

// ---------------- 10. adj: tf32x3 mma, raw cp.async dbuf, frag-time split ----
#define SPITCH 36
#define RAWSZ  (128*SPITCH)
#define ADJ_SMEM (4*RAWSZ*4)

__global__ void __launch_bounds__(512) k_adj() {
    extern __shared__ float sm[];
    float* rawA = sm;
    float* rawB = sm + 2 * RAWSZ;
    int b  = blockIdx.z;
    int n0 = blockIdx.y * 128;
    int m0 = blockIdx.x * 128;
    int tid = threadIdx.x;
    int lane = tid & 31, w = tid >> 5;
    int wm = (w >> 2) * 32;
    int wn = (w & 3) * 32;

    const float* Ag = &g_adp[((size_t)b * NP + n0) * HSZ];
    const float* Bg = &g_x1 [((size_t)b * NP + m0) * HSZ];

    float acc[2][4][4];
    #pragma unroll
    for (int mi = 0; mi < 2; ++mi)
        #pragma unroll
        for (int ni = 0; ni < 4; ++ni)
            #pragma unroll
            for (int q = 0; q < 4; ++q) acc[mi][ni][q] = 0.f;

    #pragma unroll
    for (int q = 0; q < 2; ++q) {
        int idx = tid + q * 512;
        int r = idx >> 3, c = (idx & 7) * 4;
        cp16(&rawA[r * SPITCH + c], &Ag[(size_t)r * HSZ + c]);
        cp16(&rawB[r * SPITCH + c], &Bg[(size_t)r * HSZ + c]);
    }
    cp_commit();

    for (int kt = 0; kt < 4; ++kt) {
        int buf = kt & 1;
        if (kt + 1 < 4) {
            int k0 = (kt + 1) * 32;
            float* dA = rawA + (buf ^ 1) * RAWSZ;
            float* dB = rawB + (buf ^ 1) * RAWSZ;
            #pragma unroll
            for (int q = 0; q < 2; ++q) {
                int idx = tid + q * 512;
                int r = idx >> 3, c = (idx & 7) * 4;
                cp16(&dA[r * SPITCH + c], &Ag[(size_t)r * HSZ + k0 + c]);
                cp16(&dB[r * SPITCH + c], &Bg[(size_t)r * HSZ + k0 + c]);
            }
            cp_commit();
            cp_wait<1>();
        } else {
            cp_wait<0>();
        }
        __syncthreads();

        const float* cA = rawA + buf * RAWSZ;
        const float* cB = rawB + buf * RAWSZ;
        #pragma unroll
        for (int ks = 0; ks < 4; ++ks) {
            int kc = ks * 8 + (lane & 3);
            uint32_t AhF[2][4], AlF[2][4], BhF[4][2], BlF[4][2];
            #pragma unroll
            for (int mi = 0; mi < 2; ++mi) {
                int o = (wm + mi * 16 + (lane >> 2)) * SPITCH + kc;
                float h, l;
                msplit(cA[o],                  h, l); AhF[mi][0] = __float_as_uint(h); AlF[mi][0] = __float_as_uint(l);
                msplit(cA[o + 8 * SPITCH],     h, l); AhF[mi][1] = __float_as_uint(h); AlF[mi][1] = __float_as_uint(l);
                msplit(cA[o + 4],              h, l); AhF[mi][2] = __float_as_uint(h); AlF[mi][2] = __float_as_uint(l);
                msplit(cA[o + 8 * SPITCH + 4], h, l); AhF[mi][3] = __float_as_uint(h); AlF[mi][3] = __float_as_uint(l);
            }
            #pragma unroll
            for (int ni = 0; ni < 4; ++ni) {
                int o = (wn + ni * 8 + (lane >> 2)) * SPITCH + kc;
                float h, l;
                msplit(cB[o],     h, l); BhF[ni][0] = __float_as_uint(h); BlF[ni][0] = __float_as_uint(l);
                msplit(cB[o + 4], h, l); BhF[ni][1] = __float_as_uint(h); BlF[ni][1] = __float_as_uint(l);
            }
            #pragma unroll
            for (int mi = 0; mi < 2; ++mi)
                #pragma unroll
                for (int ni = 0; ni < 4; ++ni) {
                    mma_tf32(acc[mi][ni], AhF[mi], BhF[ni]);
                    mma_tf32(acc[mi][ni], AhF[mi], BlF[ni]);
                    mma_tf32(acc[mi][ni], AlF[mi], BhF[ni]);
                }
        }
        __syncthreads();
    }

    float* abase = &g_adj[(size_t)b * NSZ * NSZ];
    #pragma unroll
    for (int mi = 0; mi < 2; ++mi) {
        int r = n0 + wm + mi * 16 + (lane >> 2);
        #pragma unroll
        for (int ni = 0; ni < 4; ++ni) {
            int c = m0 + wn + ni * 8 + ((lane & 3) << 1);
            float* C = acc[mi][ni];
            if (r < NSZ) {
                float* row = abase + (size_t)r * NSZ;
                if (c     < NSZ) row[c]     = fmaxf(C[0], 0.f);
                if (c + 1 < NSZ) row[c + 1] = fmaxf(C[1], 0.f);
            }
            if (r + 8 < NSZ) {
                float* row = abase + (size_t)(r + 8) * NSZ;
                if (c     < NSZ) row[c]     = fmaxf(C[2], 0.f);
                if (c + 1 < NSZ) row[c + 1] = fmaxf(C[3], 0.f);
            }
        }
    }
}

// ---------------- 11. per-row radix-select top-20 + softmax (early exit) -----
#define MAXEQ 64
__global__ void __launch_bounds__(256) k_topk(float* __restrict__ out) {
    int n = blockIdx.x, b = blockIdx.y, tid = threadIdx.x;
    const float* row = &g_adj[((size_t)b * NSZ + n) * NSZ];

    unsigned v[8];
    #pragma unroll
    for (int j = 0; j < 8; ++j) {
        int m = tid + j * 256;
        v[j] = (m < NSZ) ? __float_as_uint(row[m]) : 0u;
    }

    __shared__ unsigned hist[256];
    __shared__ unsigned s_bin, s_kneed, s_cnt, s_maxb, s_T;
    __shared__ unsigned warpmax[8];
    __shared__ float s_red[256];
    __shared__ float sD;
    __shared__ int eqn, eqselN;
    __shared__ int eqlist[MAXEQ];
    __shared__ int eqsel[KTOP];

    unsigned mx = v[0];
    #pragma unroll
    for (int j = 1; j < 8; ++j) mx = max(mx, v[j]);
    #pragma unroll
    for (int s = 16; s; s >>= 1) mx = max(mx, __shfl_xor_sync(0xffffffffu, mx, s));
    if (!(tid & 31)) warpmax[tid >> 5] = mx;
    if (tid == 0) eqn = 0;
    __syncthreads();
    if (tid == 0) {
        unsigned m2 = warpmax[0];
        #pragma unroll
        for (int i = 1; i < 8; ++i) m2 = max(m2, warpmax[i]);
        s_maxb = m2;
    }

    unsigned prefix = 0, mask = 0, Kneed = KTOP;
    unsigned T = 0;
    for (int pass = 0; pass < 4; ++pass) {
        int shift = 24 - pass * 8;
        __syncthreads();
        hist[tid] = 0;
        __syncthreads();
        #pragma unroll
        for (int j = 0; j < 8; ++j) {
            int m = tid + j * 256;
            if (m < NSZ && (v[j] & mask) == prefix)
                atomicAdd(&hist[(v[j] >> shift) & 255], 1u);
        }
        __syncthreads();
        if (tid < 32) {
            unsigned s = 0;
            #pragma unroll
            for (int k = 0; k < 8; ++k) s += hist[tid * 8 + k];
            unsigned suf = s;
            #pragma unroll
            for (int d = 1; d < 32; d <<= 1) {
                unsigned o = __shfl_down_sync(0xffffffffu, suf, d);
                if (tid + d < 32) suf += o;
            }
            unsigned above = suf - s;
            if (above < Kneed && above + s >= Kneed) {
                unsigned cum = above;
                for (int k = 7; k >= 0; --k) {
                    unsigned h = hist[tid * 8 + k];
                    if (cum + h >= Kneed) {
                        s_bin = tid * 8 + k; s_kneed = Kneed - cum; s_cnt = h;
                        break;
                    }
                    cum += h;
                }
            }
        }
        __syncthreads();
        prefix |= s_bin << shift;
        mask   |= 0xFFu << shift;
        Kneed   = s_kneed;
        if (pass == 3) { T = prefix; break; }
        if (s_cnt == 1) {
            // boundary bin is a singleton: that element IS the 20th largest
            #pragma unroll
            for (int j = 0; j < 8; ++j) {
                int m = tid + j * 256;
                if (m < NSZ && (v[j] & mask) == prefix) s_T = v[j];
            }
            __syncthreads();
            T = s_T;                 // Kneed == 1 here by construction
            break;
        }
    }
    float Tf   = __uint_as_float(T);
    float vmax = __uint_as_float(s_maxb);

    #pragma unroll
    for (int j = 0; j < 8; ++j) {
        int m = tid + j * 256;
        if (m < NSZ && v[j] == T) {
            int p = atomicAdd(&eqn, 1);
            if (p < MAXEQ) eqlist[p] = m;
        }
    }
    __syncthreads();
    if (tid == 0) {
        int cnt = eqn < MAXEQ ? eqn : MAXEQ;
        int need = (int)Kneed; if (need > KTOP) need = KTOP;
        int sel = 0;
        for (int a = 0; a < need && a < cnt; ++a) {
            int bi = a;
            for (int c = a + 1; c < cnt; ++c) if (eqlist[c] < eqlist[bi]) bi = c;
            int t2 = eqlist[a]; eqlist[a] = eqlist[bi]; eqlist[bi] = t2;
            eqsel[a] = eqlist[a]; ++sel;
        }
        eqselN = sel;
    }
    __syncthreads();

    float s = 0.f;
    #pragma unroll
    for (int j = 0; j < 8; ++j) {
        int m = tid + j * 256;
        if (m < NSZ && v[j] > T) s += expf(__uint_as_float(v[j]) - vmax);
    }
    s_red[tid] = s; __syncthreads();
    for (int st = 128; st; st >>= 1) {
        if (tid < st) s_red[tid] += s_red[tid + st];
        __syncthreads();
    }
    if (tid == 0)
        sD = s_red[0] + (float)eqselN * expf(Tf - vmax)
           + (float)(NSZ - KTOP) * expf(-vmax);
    __syncthreads();

    float D = sD;
    float base = expf(-vmax) / D;
    float* orow = &out[((size_t)b * NSZ + n) * NSZ];
    float4 b4 = make_float4(base, base, base, base);
    for (int i = tid; i < NSZ / 4; i += 256) ((float4*)orow)[i] = b4;
    __syncthreads();
    int nEq = eqselN;
    #pragma unroll
    for (int j = 0; j < 8; ++j) {
        int m = tid + j * 256;
        if (m < NSZ) {
            if (v[j] > T) {
                orow[m] = expf(__uint_as_float(v[j]) - vmax) / D;
            } else if (v[j] == T) {
                for (int a = 0; a < nEq; ++a)
                    if (eqsel[a] == m) { orow[m] = expf(Tf - vmax) / D; break; }
            }
        }
    }
}

// ---------------- launch ----------------
extern "C" void kernel_launch(void* const* d_in, const int* in_sizes, int n_in,
                              void* d_out, int out_size) {
    const float* x     = (const float*)d_in[0];
    const float* Ex    = (const float*)d_in[1];
    const float* nodes = (const float*)d_in[2];
    const float* Wd    = (const float*)d_in[3];
    const float* W     = (const float*)d_in[4];
    float* out = (float*)d_out;

    cudaFuncSetAttribute(k_xe,  cudaFuncAttributeMaxDynamicSharedMemorySize, XE_SMEM);
    cudaFuncSetAttribute(k_adp, cudaFuncAttributeMaxDynamicSharedMemorySize, ADP_SMEM);
    cudaFuncSetAttribute(k_adj, cudaFuncAttributeMaxDynamicSharedMemorySize, ADJ_SMEM);

    k_basis<<<(FLSZ * TSZ + 255) / 256, 256>>>();
    k_dummy<<<1, 32>>>();
    k_dummy<<<1, 32>>>();                       // k_dft stays at ncu capture index
    k_dft  <<<dim3(16, 5, BQ), 256>>>(x);
    k_invn <<<dim3(FLSZ, BQ), 256>>>();
    k_invf <<<dim3((NSZ + 63) / 64, BQ), 256>>>();
    k_xe   <<<dim3(16, 1, BQ), 512, XE_SMEM>>>(Ex);
    k_x1   <<<NSZ, 128>>>(nodes, Wd);
    k_ln1  <<<dim3(8, BQ), 256>>>();
    k_ln2  <<<1, 32>>>();
    k_wcs  <<<1, 128>>>(W);
    k_adp  <<<dim3(16, 1, BQ), 512, ADP_SMEM>>>(W);
    k_adj  <<<dim3(16, 16, BQ), 512, ADJ_SMEM>>>();
    k_topk <<<dim3(NSZ, BQ), 256>>>(out);
}